// round 10
// baseline (speedup 1.0000x reference)
#include <cuda_runtime.h>
#include <cstdint>
#include <cstddef>

#define Bq 64
#define Sq 256
#define Hq 1024
#define Lq 4
#define H2q 2048
#define H3q 3072
#define NCTA 256
#define NTHR 256
#define CPL 64                        // CTAs per layer
#define NPH (Sq + Lq - 1)
#define GA 4096                       // A floats per chunk (64 rows x 64 k)
#define GSTG 7168                     // max stage floats (GRU: 4096 A + 3072 B)
#define SMEM_BYTES (4 * GSTG * 4)     // 114688 B per CTA, 2 CTAs/SM

// ---------------- persistent device scratch ----------------
__device__ __align__(16) float g_hbuf[2][Lq][Bq][Hq];   // fp32 state (elementwise)
__device__ __align__(16) float g_hbf[2][Lq][Bq * Hq];   // tf32 fragment copy (GEMM A)
__device__ __align__(16) float g_hgru[Lq][Bq][Hq];      // fp32 GRU out (sort + gates)
__device__ __align__(16) float g_hgf[Lq][Bq * Hq];      // fragment copy (fc0 A)
__device__ __align__(16) float g_sf[Lq][Bq * Hq];       // sorted, fragment
__device__ __align__(16) float g_a0f[Lq][Bq * H2q];     // a0 shuffled, fragment
__device__ __align__(16) float g_a1f[Lq][Bq * H2q];     // a1 shuffled, fragment
__device__ __align__(16) float g_a2f[Lq][Bq * H2q];     // relu(a2), fragment
__device__ __align__(16) float g_xf[Sq * Bq * Hq];      // x, fragment per t
// fragment-major tf32 weights
__device__ __align__(16) float g_wihf[Lq * H3q * Hq];
__device__ __align__(16) float g_whhf[Lq * H3q * Hq];
__device__ __align__(16) float g_w0f[Lq * Hq * Hq];
__device__ __align__(16) float g_w1f[Lq * 512 * 512];
__device__ __align__(16) float g_w2f[Lq * 512 * 512];
__device__ __align__(16) float g_w3f[Lq * Hq * H2q];

__device__ unsigned g_cnt = 0;
__device__ volatile unsigned g_gen = 0;
__device__ unsigned g_lcnt[Lq] = {0, 0, 0, 0};
__device__ volatile unsigned g_lgen[Lq] = {0, 0, 0, 0};

// ---------------- helpers ----------------
__device__ __forceinline__ uint32_t f2tf(float f) {
    uint32_t u;
    asm("cvt.rna.tf32.f32 %0, %1;" : "=r"(u) : "f"(f));
    return u;
}
__device__ __forceinline__ float tftrunc(float f) { return __uint_as_float(f2tf(f)); }
__device__ __forceinline__ void mma8(float* c, uint32_t a0, uint32_t a1, uint32_t a2, uint32_t a3,
                                     uint32_t b0, uint32_t b1) {
    asm volatile(
        "mma.sync.aligned.m16n8k8.row.col.f32.tf32.tf32.f32 "
        "{%0,%1,%2,%3},{%4,%5,%6,%7},{%8,%9},{%0,%1,%2,%3};"
        : "+f"(c[0]), "+f"(c[1]), "+f"(c[2]), "+f"(c[3])
        : "r"(a0), "r"(a1), "r"(a2), "r"(a3), "r"(b0), "r"(b1));
}
__device__ __forceinline__ float sigmoidf_(float x) { return 1.0f / (1.0f + __expf(-x)); }

__device__ __forceinline__ void cpa16(void* dst, const void* src) {
    uint32_t d = (uint32_t)__cvta_generic_to_shared(dst);
    asm volatile("cp.async.cg.shared.global [%0], [%1], 16;" :: "r"(d), "l"(src));
}
#define CP_COMMIT() asm volatile("cp.async.commit_group;")
__device__ __forceinline__ void cpwait(int left) {
    if (left >= 2)      asm volatile("cp.async.wait_group 2;");
    else if (left == 1) asm volatile("cp.async.wait_group 1;");
    else                asm volatile("cp.async.wait_group 0;");
}

// fragment index for 64-row A tensors: [kb=col>>3][mb=row>>4][lane32][slot4]
__device__ __forceinline__ int afidx(int row, int col) {
    return ((((col >> 3) << 2) + (row >> 4)) * 32 + ((row & 7) * 4 + (col & 3))) * 4
         + ((((col & 7) >> 2) << 1) + ((row & 15) >> 3));
}

// ---------------- barriers ----------------
__device__ __forceinline__ void gridbar() {
    __threadfence();
    __syncthreads();
    if (threadIdx.x == 0) {
        unsigned gen = g_gen;
        if (atomicAdd(&g_cnt, 1u) == NCTA - 1) {
            g_cnt = 0;
            __threadfence();
            g_gen = gen + 1;
        } else {
            while (g_gen == gen) __nanosleep(64);
        }
    }
    __syncthreads();
}
__device__ __forceinline__ void layerbar(int l) {
    __threadfence();
    __syncthreads();
    if (threadIdx.x == 0) {
        unsigned gen = g_lgen[l];
        if (atomicAdd(&g_lcnt[l], 1u) == CPL - 1) {
            g_lcnt[l] = 0;
            __threadfence();
            g_lgen[l] = gen + 1;
        } else {
            while (g_lgen[l] == gen) __nanosleep(32);
        }
    }
    __syncthreads();
}

// ---------------- weight permute: row-major [N][K] -> fragment-major ----------------
__device__ __forceinline__ void permW(float* dst, const float* src, int N, int K,
                                      int gid, int gsz) {
    const int NB = N >> 3;
    const size_t tot = (size_t)N * K;
    for (size_t i = gid; i < tot; i += gsz) {
        int s = (int)(i & 3);
        int lane = (int)((i >> 2) & 31);
        int kb2 = (int)((i >> 7) & 3);
        size_t hi = i >> 9;
        int nb = (int)(hi % NB);
        int c = (int)(hi / NB);
        int r = nb * 8 + (lane >> 2);
        int k = c * 64 + kb2 * 16 + ((s >> 1) << 3) + ((s & 1) << 2) + (lane & 3);
        dst[i] = tftrunc(__ldg(src + (size_t)r * K + k));
    }
}

// one K64 chunk, m32n16 per warp (A 64 rows in smem, warp rows = wm*32..+32)
#define GCHUNK(ACC) { \
    const float* A_ = dyn + sg * GSTG; \
    const uint4* Bf_ = (const uint4*)(dyn + sg * GSTG + GA + st * 1024); \
    _Pragma("unroll") \
    for (int kb2 = 0; kb2 < 4; kb2++) { \
        uint4 b0_ = Bf_[kb2 * 32 + lane]; \
        uint4 b1_ = Bf_[(4 + kb2) * 32 + lane]; \
        _Pragma("unroll") \
        for (int pp = 0; pp < 2; pp++) { \
            _Pragma("unroll") \
            for (int mt = 0; mt < 2; mt++) { \
                uint4 aq = *(const uint4*)(A_ + ((kb2 * 2 + pp) * 4 + wm * 2 + mt) * 128 + lane * 4); \
                mma8(ACC[mt][0], aq.x, aq.y, aq.z, aq.w, pp ? b0_.z : b0_.x, pp ? b0_.w : b0_.y); \
                mma8(ACC[mt][1], aq.x, aq.y, aq.z, aq.w, pp ? b1_.z : b1_.x, pp ? b1_.w : b1_.y); \
            } \
        } \
    } \
}

// ---------------- GRU stage: 16 H-cols/CTA, 6 compute warps (3 streams x m32) -----
__device__ __forceinline__ void gru_stage(float* dyn, int l, int t, int n0,
    const float* __restrict__ bih, const float* __restrict__ bhh)
{
    const int par = t & 1;
    const int tid = threadIdx.x;
    const int warp = tid >> 5, lane = tid & 31;
    const int st = warp >> 1, wm = warp & 1;     // stream, m32 half (warp<6)
    const int grp = lane >> 2, tig = lane & 3;

    const float* Af1 = (l == 0) ? (g_xf + (size_t)t * 65536) : g_hbf[par][l - 1];
    const float* Af2 = g_hbf[par ^ 1][l];
    const float* Wih_ = g_wihf + (size_t)l * H3q * Hq;
    const float* Whh_ = g_whhf + (size_t)l * H3q * Hq;

    auto issue = [&](int c, int sg) {
        float* A = dyn + sg * GSTG;
        float* B = A + GA;
        const float* as = (c < 16) ? (Af1 + (size_t)c * 4096)
                                   : (Af2 + (size_t)(c - 16) * 4096);
#pragma unroll
        for (int i = 0; i < 4; i++)
            cpa16(A + (tid + i * 256) * 4, as + (size_t)(tid + i * 256) * 4);
        const float* wmat = (c < 16) ? Wih_ : Whh_;
        const int cc = c & 15;
#pragma unroll
        for (int s3 = 0; s3 < 3; s3++) {
            const float* ws = wmat + ((size_t)(cc * 384 + s3 * 128 + (n0 >> 3))) * 512;
            cpa16(B + s3 * 1024 + tid * 4, ws + tid * 4);
        }
        CP_COMMIT();
    };

    float acc1[2][2][4] = {};    // R/Z full, or N(ih) for stream 2
    float acc2[2][2][4] = {};    // N(hh) for stream 2

    issue(0, 0); issue(1, 1); issue(2, 2);
    for (int c = 0; c < 16; c++) {
        cpwait(31 - c);
        __syncthreads();
        issue(c + 3, (c + 3) & 3);
        if (warp < 6) {
            const int sg = c & 3;
            GCHUNK(acc1);
        }
    }
    for (int c = 16; c < 32; c++) {
        cpwait(31 - c);
        __syncthreads();
        if (c + 3 < 32) issue(c + 3, (c + 3) & 3);
        if (warp < 6) {
            const int sg = c & 3;
            if (st == 2) { GCHUNK(acc2); } else { GCHUNK(acc1); }
        }
    }
    __syncthreads();

    // stage accumulators (R,Z,Ni,Nh), then combine gates
    float (*E)[64][16] = (float(*)[64][16])dyn;
    if (warp < 6) {
#pragma unroll
        for (int mt = 0; mt < 2; mt++)
#pragma unroll
            for (int ns = 0; ns < 2; ns++)
#pragma unroll
                for (int e = 0; e < 4; e++) {
                    int row = wm * 32 + mt * 16 + grp + ((e >> 1) << 3);
                    int col = ns * 8 + tig * 2 + (e & 1);
                    if (st < 2) E[st][row][col] = acc1[mt][ns][e];
                    else { E[2][row][col] = acc1[mt][ns][e]; E[3][row][col] = acc2[mt][ns][e]; }
                }
    }
    __syncthreads();

    const float* bi = bih + l * H3q;
    const float* bh = bhh + l * H3q;
#pragma unroll
    for (int e = 0; e < 4; e++) {
        int q = tid + e * 256;
        int m = q >> 4, n = q & 15, col = n0 + n;
        float r  = sigmoidf_(E[0][m][n] + __ldg(bi + col) + __ldg(bh + col));
        float z  = sigmoidf_(E[1][m][n] + __ldg(bi + Hq + col) + __ldg(bh + Hq + col));
        float nn = tanhf(E[2][m][n] + __ldg(bi + 2 * Hq + col)
                         + r * (E[3][m][n] + __ldg(bh + 2 * Hq + col)));
        float hp = __ldcg(&g_hbuf[par ^ 1][l][m][col]);
        float hv = (1.0f - z) * nn + z * hp;
        g_hgru[l][m][col] = hv;
        g_hgf[l][afidx(m, col)] = tftrunc(hv);
    }
    __syncthreads();
}

// ---------------- 1-row-per-CTA bitonic sort (ascending, 1024 elems) ------------
__device__ __forceinline__ void sort_rows(float* dyn, int l, int b) {
    const int tid = threadIdx.x;
    float* s = dyn;
#pragma unroll
    for (int e = 0; e < 4; e++) s[tid + (e << 8)] = __ldcg(&g_hgru[l][b][tid + (e << 8)]);
    __syncthreads();
    for (int k = 2; k <= 1024; k <<= 1) {
        for (int j = k >> 1; j > 0; j >>= 1) {
#pragma unroll
            for (int e = 0; e < 2; e++) {
                int tc = tid + (e << 8);
                int pos = ((tc & ~(j - 1)) << 1) | (tc & (j - 1));
                int q = pos | j;
                bool up = ((pos & k) == 0);
                float a = s[pos], bb = s[q];
                if ((a > bb) == up) { s[pos] = bb; s[q] = a; }
            }
            __syncthreads();
        }
    }
#pragma unroll
    for (int e = 0; e < 4; e++) {
        int pos = tid + (e << 8);
        g_sf[l][afidx(b, pos)] = tftrunc(s[pos]);
    }
    __syncthreads();
}

// ---------------- generic FC stage (8 compute warps) ----------------
// MODE 0: a0 = [h|sorted]@w0^T (K=1024, NT=32) -> stored shuffled
// MODE 1: a1 = a0s@w1^T        (K=512,  NT=32) -> stored shuffled
// MODE 2: a2 = relu(a1s@w2^T)  (K=512,  NT=32) -> linear
// MODE 3: h' = hgru*sigmoid(a2@w3^T) (K=2048, NT=16) -> hbuf + outs(l==3)
template <int MODE>
__device__ __forceinline__ void fc_stage(float* dyn, int l, int t, int n0,
                                         float* __restrict__ outp)
{
    constexpr int NCH = (MODE == 0) ? 16 : (MODE == 3 ? 32 : 8);
    constexpr int NT = (MODE == 3) ? 16 : 32;
    constexpr int NSUB = NT / 16;                // 2 or 1
    constexpr int BN = NT / 16;                  // B cp.async per thread

    const int tid = threadIdx.x;
    const int warp = tid >> 5, lane = tid & 31;
    const int wm = warp & 3, wn = warp >> 2;
    const int grp = lane >> 2, tig = lane & 3;

    const float* Af;
    if constexpr (MODE == 0)      Af = (n0 >= Hq) ? g_sf[l] : g_hgf[l];
    else if constexpr (MODE == 1) Af = g_a0f[l] + ((size_t)(n0 >> 9) << 15);
    else if constexpr (MODE == 2) Af = g_a1f[l] + ((size_t)(n0 >> 9) << 15);
    else                          Af = g_a2f[l];

    const float* Wf; int o0; int NBALL;
    if constexpr (MODE == 0)      { Wf = g_w0f + (size_t)l * Hq * Hq;   o0 = n0 & (Hq - 1); NBALL = 128; }
    else if constexpr (MODE == 1) { Wf = g_w1f + (size_t)l * 512 * 512; o0 = n0 & 511;      NBALL = 64; }
    else if constexpr (MODE == 2) { Wf = g_w2f + (size_t)l * 512 * 512; o0 = n0 & 511;      NBALL = 64; }
    else                          { Wf = g_w3f + (size_t)l * Hq * H2q;  o0 = n0;            NBALL = 128; }

    auto issue = [&](int c, int sg) {
        float* A = dyn + sg * GSTG;
        float* B = A + GA;
        const float* as = Af + (size_t)c * 4096;
#pragma unroll
        for (int i = 0; i < 4; i++)
            cpa16(A + (tid + i * 256) * 4, as + (size_t)(tid + i * 256) * 4);
        const float* ws = Wf + ((size_t)c * NBALL + (o0 >> 3)) * 512;
#pragma unroll
        for (int i = 0; i < BN; i++)
            cpa16(B + (tid + i * 256) * 4, ws + (size_t)(tid + i * 256) * 4);
        CP_COMMIT();
    };

    float acc[NSUB][4];
#pragma unroll
    for (int i = 0; i < NSUB; i++) { acc[i][0] = acc[i][1] = acc[i][2] = acc[i][3] = 0.f; }

    issue(0, 0); issue(1, 1); issue(2, 2);
    for (int c = 0; c < NCH; c++) {
        cpwait(NCH - 1 - c);
        __syncthreads();
        if (c + 3 < NCH) issue(c + 3, (c + 3) & 3);
        {
            const int sg = c & 3;
            const float* A_ = dyn + sg * GSTG;
            const uint4* Bf_ = (const uint4*)(dyn + sg * GSTG + GA);
#pragma unroll
            for (int kb2 = 0; kb2 < 4; kb2++) {
                uint4 bq[NSUB];
#pragma unroll
                for (int ns = 0; ns < NSUB; ns++)
                    bq[ns] = Bf_[((wn * NSUB + ns) * 4 + kb2) * 32 + lane];
#pragma unroll
                for (int pp = 0; pp < 2; pp++) {
                    uint4 aq = *(const uint4*)(A_ + ((kb2 * 2 + pp) * 4 + wm) * 128 + lane * 4);
#pragma unroll
                    for (int ns = 0; ns < NSUB; ns++)
                        mma8(acc[ns], aq.x, aq.y, aq.z, aq.w,
                             pp ? bq[ns].z : bq[ns].x, pp ? bq[ns].w : bq[ns].y);
                }
            }
        }
    }
    __syncthreads();

#pragma unroll
    for (int ns = 0; ns < NSUB; ns++)
#pragma unroll
        for (int e = 0; e < 4; e++) {
            int row = wm * 16 + grp + ((e >> 1) << 3);
            int cl = wn * (NSUB * 8) + ns * 8 + tig * 2 + (e & 1);
            int cg = n0 + cl;
            float v = acc[ns][e];
            if constexpr (MODE == 0) {
                int p = 4 * (cg & 511) + (cg >> 9);
                g_a0f[l][afidx(row, p)] = tftrunc(v);
            } else if constexpr (MODE == 1) {
                int p = 4 * (cg & 511) + (cg >> 9);
                g_a1f[l][afidx(row, p)] = tftrunc(v);
            } else if constexpr (MODE == 2) {
                g_a2f[l][afidx(row, cg)] = tftrunc(fmaxf(v, 0.0f));
            } else {
                float val = __ldcg(&g_hgru[l][row][cg]) * sigmoidf_(v);
                g_hbuf[t & 1][l][row][cg] = val;
                g_hbf[t & 1][l][afidx(row, cg)] = tftrunc(val);
                if (l == Lq - 1)
                    outp[((size_t)row * Sq + t) * Hq + cg] = val;
            }
        }
    __syncthreads();
}

// ---------------- the single persistent kernel ----------------
__global__ void __launch_bounds__(NTHR, 2) fss_persist_kernel(
    const float* __restrict__ x, const float* __restrict__ h0,
    const float* __restrict__ Wih, const float* __restrict__ Whh,
    const float* __restrict__ bih, const float* __restrict__ bhh,
    const float* __restrict__ aw0, const float* __restrict__ aw1,
    const float* __restrict__ aw2, const float* __restrict__ aw3,
    float* __restrict__ outp, int out_size)
{
    extern __shared__ float dyn[];
    const int bx = blockIdx.x, tid = threadIdx.x;
    const int gid = bx * NTHR + tid, gsz = NCTA * NTHR;

    // --- one-time-per-launch permutes (fragment-major, tf32 pre-rounded) ---
    for (int l0 = 0; l0 < Lq; l0++) {
        permW(g_wihf + (size_t)l0 * H3q * Hq, Wih + (size_t)l0 * H3q * Hq, H3q, Hq, gid, gsz);
        permW(g_whhf + (size_t)l0 * H3q * Hq, Whh + (size_t)l0 * H3q * Hq, H3q, Hq, gid, gsz);
        permW(g_w0f + (size_t)l0 * Hq * Hq,   aw0 + (size_t)l0 * Hq * Hq,  Hq, Hq, gid, gsz);
        permW(g_w1f + (size_t)l0 * 512 * 512, aw1 + (size_t)l0 * 512 * 512, 512, 512, gid, gsz);
        permW(g_w2f + (size_t)l0 * 512 * 512, aw2 + (size_t)l0 * 512 * 512, 512, 512, gid, gsz);
        permW(g_w3f + (size_t)l0 * Hq * H2q,  aw3 + (size_t)l0 * Hq * H2q, Hq, H2q, gid, gsz);
    }
    // x -> per-timestep fragment layout
    for (size_t i = gid; i < (size_t)Sq * 65536; i += gsz) {
        int j = (int)(i & 65535);
        int t = (int)(i >> 16);
        int s = j & 3, lane = (j >> 2) & 31, mb = (j >> 7) & 3, kb = j >> 9;
        int row = mb * 16 + (lane >> 2) + ((s & 1) << 3);
        int col = kb * 8 + (lane & 3) + ((s >> 1) << 2);
        g_xf[i] = tftrunc(__ldg(x + ((size_t)row * Sq + t) * Hq + col));
    }
    // h0 -> parity-1 buffers (linear + fragment); t=0 reads parity 1
    for (int i = gid; i < Lq * 65536; i += gsz) {
        int l0 = i >> 16, j = i & 65535;
        int b = j >> 10, k = j & (Hq - 1);
        g_hbuf[1][l0][b][k] = h0[l0 * Hq + k];
        int s = j & 3, lane = (j >> 2) & 31, kb = j >> 9;
        int col = kb * 8 + (lane & 3) + ((s >> 1) << 2);
        g_hbf[1][l0][j] = tftrunc(h0[l0 * Hq + col]);
    }
    gridbar();

    const int l = bx >> 6, idx = bx & 63;
    for (int p = 0; p < NPH; ++p) {
        const int t = p - l;
        if (t >= 0 && t < Sq) {
            gru_stage(dyn, l, t, idx * 16, bih, bhh);
            layerbar(l);
            sort_rows(dyn, l, idx);
            layerbar(l);
            fc_stage<0>(dyn, l, t, idx * 32, outp);
            layerbar(l);
            fc_stage<1>(dyn, l, t, idx * 32, outp);
            layerbar(l);
            fc_stage<2>(dyn, l, t, idx * 32, outp);
            layerbar(l);
            fc_stage<3>(dyn, l, t, idx * 16, outp);
        }
        gridbar();
    }

    // final hidden state hT (t=255 -> parity 1), layout (L,B,H)
    if (out_size >= Bq * Sq * Hq + Lq * Bq * Hq) {
        for (int i = gid; i < Lq * Bq * Hq; i += gsz)
            outp[(size_t)Bq * Sq * Hq + i] = __ldcg(&(&g_hbuf[1][0][0][0])[i]);
    }
}

// ---------------- launch ----------------
extern "C" void kernel_launch(void* const* d_in, const int* in_sizes, int n_in,
                              void* d_out, int out_size) {
    (void)in_sizes; (void)n_in;
    cudaFuncSetAttribute(fss_persist_kernel,
                         cudaFuncAttributeMaxDynamicSharedMemorySize, SMEM_BYTES);
    fss_persist_kernel<<<NCTA, NTHR, SMEM_BYTES>>>(
        (const float*)d_in[0], (const float*)d_in[1],
        (const float*)d_in[2], (const float*)d_in[3],
        (const float*)d_in[4], (const float*)d_in[5],
        (const float*)d_in[6], (const float*)d_in[7],
        (const float*)d_in[8], (const float*)d_in[9],
        (float*)d_out, out_size);
}

// round 11
// speedup vs baseline: 1.0185x; 1.0185x over previous
#include <cuda_runtime.h>
#include <cstdint>
#include <cstddef>

#define Bq 64
#define Sq 256
#define Hq 1024
#define Lq 4
#define H2q 2048
#define H3q 3072
#define NCTA 128
#define NTHR 512
#define GA 4096                       // A floats per chunk (64 rows x 64 k)
#define GB 6144                       // GRU B floats per chunk (96 rows x 64 k)
#define GSTG (GA + GB)                // floats per pipeline stage
#define SMEM_BYTES (4 * GSTG * 4)     // 163840 B

// ---------------- persistent device scratch ----------------
__device__ __align__(16) float g_hbuf[2][Lq][Bq][Hq];   // fp32 state (elementwise)
__device__ __align__(16) float g_hbf[2][Lq][Bq * Hq];   // tf32 fragment copy (GEMM A)
__device__ __align__(16) float g_hgru[Lq][Bq][Hq];      // fp32 GRU out (sort + gates)
__device__ __align__(16) float g_hgf[Lq][Bq * Hq];      // fragment copy (fc0 A)
__device__ __align__(16) float g_sf[Lq][Bq * Hq];       // sorted, fragment
__device__ __align__(16) float g_a0f[Lq][Bq * H2q];     // a0 shuffled, fragment
__device__ __align__(16) float g_a1f[Lq][Bq * H2q];     // a1 shuffled, fragment
__device__ __align__(16) float g_a2f[Lq][Bq * H2q];     // relu(a2), fragment
__device__ __align__(16) float g_xf[Sq * Bq * Hq];      // x, fragment per t
// fragment-major tf32 weights
__device__ __align__(16) float g_wihf[Lq * H3q * Hq];
__device__ __align__(16) float g_whhf[Lq * H3q * Hq];
__device__ __align__(16) float g_w0f[Lq * Hq * Hq];
__device__ __align__(16) float g_w1f[Lq * 512 * 512];
__device__ __align__(16) float g_w2f[Lq * 512 * 512];
__device__ __align__(16) float g_w3f[Lq * Hq * H2q];

__device__ unsigned g_cnt = 0;
__device__ volatile unsigned g_gen = 0;
__device__ unsigned g_lcnt[Lq] = {0, 0, 0, 0};
__device__ volatile unsigned g_lgen[Lq] = {0, 0, 0, 0};
// elastic cross-layer dataflow counters (reset every launch)
__device__ volatile int g_done_t[Lq];      // last timestep fully completed by layer l
__device__ volatile int g_grudone_t[Lq];   // last timestep whose GRU completed (h[l-1] consumed)

// ---------------- helpers ----------------
__device__ __forceinline__ uint32_t f2tf(float f) {
    uint32_t u;
    asm("cvt.rna.tf32.f32 %0, %1;" : "=r"(u) : "f"(f));
    return u;
}
__device__ __forceinline__ float tftrunc(float f) { return __uint_as_float(f2tf(f)); }
__device__ __forceinline__ void mma8(float* c, uint32_t a0, uint32_t a1, uint32_t a2, uint32_t a3,
                                     uint32_t b0, uint32_t b1) {
    asm volatile(
        "mma.sync.aligned.m16n8k8.row.col.f32.tf32.tf32.f32 "
        "{%0,%1,%2,%3},{%4,%5,%6,%7},{%8,%9},{%0,%1,%2,%3};"
        : "+f"(c[0]), "+f"(c[1]), "+f"(c[2]), "+f"(c[3])
        : "r"(a0), "r"(a1), "r"(a2), "r"(a3), "r"(b0), "r"(b1));
}
__device__ __forceinline__ float sigmoidf_(float x) { return 1.0f / (1.0f + __expf(-x)); }

__device__ __forceinline__ void cpa16(void* dst, const void* src) {
    uint32_t d = (uint32_t)__cvta_generic_to_shared(dst);
    asm volatile("cp.async.cg.shared.global [%0], [%1], 16;" :: "r"(d), "l"(src));
}
#define CP_COMMIT() asm volatile("cp.async.commit_group;")
__device__ __forceinline__ void cpwait(int left) {
    if (left >= 2)      asm volatile("cp.async.wait_group 2;");
    else if (left == 1) asm volatile("cp.async.wait_group 1;");
    else                asm volatile("cp.async.wait_group 0;");
}

// fragment index for 64-row A tensors: [kb=col>>3][mb=row>>4][lane32][slot4]
__device__ __forceinline__ int afidx(int row, int col) {
    return ((((col >> 3) << 2) + (row >> 4)) * 32 + ((row & 7) * 4 + (col & 3))) * 4
         + ((((col & 7) >> 2) << 1) + ((row & 15) >> 3));
}

// ---------------- barriers / waits ----------------
__device__ __forceinline__ void gridbar() {
    __threadfence();
    __syncthreads();
    if (threadIdx.x == 0) {
        unsigned gen = g_gen;
        if (atomicAdd(&g_cnt, 1u) == NCTA - 1) {
            g_cnt = 0;
            __threadfence();
            g_gen = gen + 1;
        } else {
            while (g_gen == gen) __nanosleep(64);
        }
    }
    __syncthreads();
}
__device__ __forceinline__ void layerbar(int l) {
    __threadfence();
    __syncthreads();
    if (threadIdx.x == 0) {
        unsigned gen = g_lgen[l];
        if (atomicAdd(&g_lcnt[l], 1u) == 31) {
            g_lcnt[l] = 0;
            __threadfence();
            g_lgen[l] = gen + 1;
        } else {
            while (g_lgen[l] == gen) __nanosleep(32);
        }
    }
    __syncthreads();
}
__device__ __forceinline__ void waitge(volatile int* p, int v) {
    if (threadIdx.x == 0) {
        while (*p < v) __nanosleep(64);
    }
    __syncthreads();
}

// ---------------- weight permute: row-major [N][K] -> fragment-major ----------------
__device__ __forceinline__ void permW(float* dst, const float* src, int N, int K,
                                      int gid, int gsz) {
    const int NB = N >> 3;
    const size_t tot = (size_t)N * K;
    for (size_t i = gid; i < tot; i += gsz) {
        int s = (int)(i & 3);
        int lane = (int)((i >> 2) & 31);
        int kb2 = (int)((i >> 7) & 3);
        size_t hi = i >> 9;
        int nb = (int)(hi % NB);
        int c = (int)(hi / NB);
        int r = nb * 8 + (lane >> 2);
        int k = c * 64 + kb2 * 16 + ((s >> 1) << 3) + ((s & 1) << 2) + (lane & 3);
        dst[i] = tftrunc(__ldg(src + (size_t)r * K + k));
    }
}

// one K64-chunk of m16n32 mma work for one warp (all-register accumulators)
#define FRAG_CHUNK(APTR, BPTR, MB, ACC) { \
    const float* A_ = (APTR); \
    const uint4* Bf_ = (const uint4*)(BPTR); \
    _Pragma("unroll") \
    for (int kb2 = 0; kb2 < 4; kb2++) { \
        uint4 b0_ = Bf_[(0 * 4 + kb2) * 32 + lane]; \
        uint4 b1_ = Bf_[(1 * 4 + kb2) * 32 + lane]; \
        uint4 b2_ = Bf_[(2 * 4 + kb2) * 32 + lane]; \
        uint4 b3_ = Bf_[(3 * 4 + kb2) * 32 + lane]; \
        _Pragma("unroll") \
        for (int pp = 0; pp < 2; pp++) { \
            uint4 aq = *(const uint4*)(A_ + ((kb2 * 2 + pp) * 4 + (MB)) * 128 + lane * 4); \
            mma8(ACC[0], aq.x, aq.y, aq.z, aq.w, pp ? b0_.z : b0_.x, pp ? b0_.w : b0_.y); \
            mma8(ACC[1], aq.x, aq.y, aq.z, aq.w, pp ? b1_.z : b1_.x, pp ? b1_.w : b1_.y); \
            mma8(ACC[2], aq.x, aq.y, aq.z, aq.w, pp ? b2_.z : b2_.x, pp ? b2_.w : b2_.y); \
            mma8(ACC[3], aq.x, aq.y, aq.z, aq.w, pp ? b3_.z : b3_.x, pp ? b3_.w : b3_.y); \
        } \
    } \
}

// ---------------- GRU stage: 32 H-cols/CTA, 12 compute warps (3 streams x 4 m16) ---
__device__ __forceinline__ void gru_stage(float* dyn, int l, int t, int n0,
    const float* __restrict__ bih, const float* __restrict__ bhh)
{
    const int par = t & 1;
    const int tid = threadIdx.x;
    const int warp = tid >> 5, lane = tid & 31;
    const int st = warp >> 2, wm = warp & 3;     // stream, m16 block (warp<12)
    const int grp = lane >> 2, tig = lane & 3;

    const float* Af1 = (l == 0) ? (g_xf + (size_t)t * 65536) : g_hbf[par][l - 1];
    const float* Af2 = g_hbf[par ^ 1][l];
    const float* Wih_ = g_wihf + (size_t)l * H3q * Hq;
    const float* Whh_ = g_whhf + (size_t)l * H3q * Hq;

    auto issue = [&](int c, int sg) {
        float* A = dyn + sg * GSTG;
        float* B = A + GA;
        const float* as = (c < 16) ? (Af1 + (size_t)c * 4096)
                                   : (Af2 + (size_t)(c - 16) * 4096);
        cpa16(A + tid * 4, as + tid * 4);
        cpa16(A + (tid + 512) * 4, as + (tid + 512) * 4);
        const float* wmat = (c < 16) ? Wih_ : Whh_;
        const int cc = c & 15;
#pragma unroll
        for (int s3 = 0; s3 < 3; s3++) {
            const float* ws = wmat + ((size_t)(cc * 384 + s3 * 128 + (n0 >> 3))) * 512;
            cpa16(B + s3 * 2048 + tid * 4, ws + tid * 4);
        }
        CP_COMMIT();
    };

    float acc1[4][4] = {};    // R/Z full, or N(ih) for stream 2
    float acc2[4][4] = {};    // N(hh) for stream 2

    issue(0, 0); issue(1, 1); issue(2, 2);
    for (int c = 0; c < 16; c++) {
        cpwait(31 - c);
        __syncthreads();
        issue(c + 3, (c + 3) & 3);
        if (warp < 12) {
            const int sg = c & 3;
            FRAG_CHUNK(dyn + sg * GSTG, dyn + sg * GSTG + GA + st * 2048, wm, acc1);
        }
    }
    for (int c = 16; c < 32; c++) {
        cpwait(31 - c);
        __syncthreads();
        if (c + 3 < 32) issue(c + 3, (c + 3) & 3);
        if (warp < 12) {
            const int sg = c & 3;
            if (st == 2) {
                FRAG_CHUNK(dyn + sg * GSTG, dyn + sg * GSTG + GA + st * 2048, wm, acc2);
            } else {
                FRAG_CHUNK(dyn + sg * GSTG, dyn + sg * GSTG + GA + st * 2048, wm, acc1);
            }
        }
    }
    __syncthreads();

    // stage accumulators (R,Z,Ni,Nh), then combine gates
    float (*E)[64][32] = (float(*)[64][32])dyn;
    if (warp < 12) {
#pragma unroll
        for (int ns = 0; ns < 4; ns++)
#pragma unroll
            for (int e = 0; e < 4; e++) {
                int row = wm * 16 + grp + ((e >> 1) << 3);
                int col = ns * 8 + tig * 2 + (e & 1);
                if (st < 2) E[st][row][col] = acc1[ns][e];
                else { E[2][row][col] = acc1[ns][e]; E[3][row][col] = acc2[ns][e]; }
            }
    }
    __syncthreads();

    const float* bi = bih + l * H3q;
    const float* bh = bhh + l * H3q;
#pragma unroll
    for (int e = 0; e < 4; e++) {
        int q = tid + e * 512;
        int m = q >> 5, n = q & 31, col = n0 + n;
        float r  = sigmoidf_(E[0][m][n] + __ldg(bi + col) + __ldg(bh + col));
        float z  = sigmoidf_(E[1][m][n] + __ldg(bi + Hq + col) + __ldg(bh + Hq + col));
        float nn = tanhf(E[2][m][n] + __ldg(bi + 2 * Hq + col)
                         + r * (E[3][m][n] + __ldg(bh + 2 * Hq + col)));
        float hp = __ldcg(&g_hbuf[par ^ 1][l][m][col]);
        float hv = (1.0f - z) * nn + z * hp;
        g_hgru[l][m][col] = hv;
        g_hgf[l][afidx(m, col)] = tftrunc(hv);
    }
    __syncthreads();
}

// ---------------- 2-rows-per-CTA bitonic sort (ascending, 1024 each) ------------
__device__ __forceinline__ void sort_rows(float* dyn, int l, int pair) {
    const int tid = threadIdx.x;
    const int sub = tid >> 8, tt = tid & 255;
    const int b = pair * 2 + sub;
    float* s = dyn + sub * 1024;
#pragma unroll
    for (int e = 0; e < 4; e++) s[tt + (e << 8)] = __ldcg(&g_hgru[l][b][tt + (e << 8)]);
    __syncthreads();
    for (int k = 2; k <= 1024; k <<= 1) {
        for (int j = k >> 1; j > 0; j >>= 1) {
#pragma unroll
            for (int e = 0; e < 2; e++) {
                int tc = tt + (e << 8);
                int pos = ((tc & ~(j - 1)) << 1) | (tc & (j - 1));
                int q = pos | j;
                bool up = ((pos & k) == 0);
                float a = s[pos], bb = s[q];
                if ((a > bb) == up) { s[pos] = bb; s[q] = a; }
            }
            __syncthreads();
        }
    }
#pragma unroll
    for (int e = 0; e < 4; e++) {
        int pos = tt + (e << 8);
        g_sf[l][afidx(b, pos)] = tftrunc(s[pos]);
    }
    __syncthreads();
}

// ---------------- generic FC stage (8 compute warps) ----------------
// MODE 0: a0 = [h|sorted]@w0^T (K=1024, NT=64) -> stored shuffled
// MODE 1: a1 = a0s@w1^T        (K=512,  NT=64) -> stored shuffled
// MODE 2: a2 = relu(a1s@w2^T)  (K=512,  NT=64) -> linear
// MODE 3: h' = hgru*sigmoid(a2@w3^T) (K=2048, NT=32) -> hbuf + outs(l==3)
template <int MODE>
__device__ __forceinline__ void fc_stage(float* dyn, int l, int t, int n0,
                                         float* __restrict__ outp)
{
    constexpr int NCH = (MODE == 0) ? 16 : (MODE == 3 ? 32 : 8);
    constexpr int NSUB = (MODE == 3) ? 2 : 4;
    constexpr int BFL = (MODE == 3) ? 2048 : 4096;

    const int tid = threadIdx.x;
    const int warp = tid >> 5, lane = tid & 31;
    const int wm = warp & 3, wn = warp >> 2;      // valid under warp<8
    const int grp = lane >> 2, tig = lane & 3;

    const float* Af;
    if constexpr (MODE == 0)      Af = (n0 >= Hq) ? g_sf[l] : g_hgf[l];
    else if constexpr (MODE == 1) Af = g_a0f[l] + ((size_t)(n0 >> 9) << 15);
    else if constexpr (MODE == 2) Af = g_a1f[l] + ((size_t)(n0 >> 9) << 15);
    else                          Af = g_a2f[l];

    const float* Wf; int o0; int NBALL;
    if constexpr (MODE == 0)      { Wf = g_w0f + (size_t)l * Hq * Hq;   o0 = n0 & (Hq - 1); NBALL = 128; }
    else if constexpr (MODE == 1) { Wf = g_w1f + (size_t)l * 512 * 512; o0 = n0 & 511;      NBALL = 64; }
    else if constexpr (MODE == 2) { Wf = g_w2f + (size_t)l * 512 * 512; o0 = n0 & 511;      NBALL = 64; }
    else                          { Wf = g_w3f + (size_t)l * Hq * H2q;  o0 = n0;            NBALL = 128; }

    auto issue = [&](int c, int sg) {
        float* A = dyn + sg * GSTG;
        float* B = A + GA;
        const float* as = Af + (size_t)c * 4096;
        cpa16(A + tid * 4, as + tid * 4);
        cpa16(A + (tid + 512) * 4, as + (tid + 512) * 4);
        const float* ws = Wf + ((size_t)c * NBALL + (o0 >> 3)) * 512;
        cpa16(B + tid * 4, ws + tid * 4);
        if (BFL == 4096) cpa16(B + (tid + 512) * 4, ws + (tid + 512) * 4);
        CP_COMMIT();
    };

    float acc[NSUB][4];
#pragma unroll
    for (int i = 0; i < NSUB; i++) { acc[i][0] = acc[i][1] = acc[i][2] = acc[i][3] = 0.f; }

    issue(0, 0); issue(1, 1); issue(2, 2);
    for (int c = 0; c < NCH; c++) {
        cpwait(NCH - 1 - c);
        __syncthreads();
        if (c + 3 < NCH) issue(c + 3, (c + 3) & 3);
        if (warp < 8) {
            const int sg = c & 3;
            const float* A_ = dyn + sg * GSTG;
            const uint4* Bf_ = (const uint4*)(dyn + sg * GSTG + GA);
#pragma unroll
            for (int kb2 = 0; kb2 < 4; kb2++) {
                uint4 bq[NSUB];
#pragma unroll
                for (int ns = 0; ns < NSUB; ns++)
                    bq[ns] = Bf_[((wn * NSUB + ns) * 4 + kb2) * 32 + lane];
#pragma unroll
                for (int pp = 0; pp < 2; pp++) {
                    uint4 aq = *(const uint4*)(A_ + ((kb2 * 2 + pp) * 4 + wm) * 128 + lane * 4);
#pragma unroll
                    for (int ns = 0; ns < NSUB; ns++)
                        mma8(acc[ns], aq.x, aq.y, aq.z, aq.w,
                             pp ? bq[ns].z : bq[ns].x, pp ? bq[ns].w : bq[ns].y);
                }
            }
        }
    }
    __syncthreads();

    if (warp < 8) {
#pragma unroll
        for (int ns = 0; ns < NSUB; ns++)
#pragma unroll
            for (int e = 0; e < 4; e++) {
                int row = wm * 16 + grp + ((e >> 1) << 3);
                int cl = wn * (NSUB * 8) + ns * 8 + tig * 2 + (e & 1);
                int cg = n0 + cl;
                float v = acc[ns][e];
                if constexpr (MODE == 0) {
                    int p = 4 * (cg & 511) + (cg >> 9);
                    g_a0f[l][afidx(row, p)] = tftrunc(v);
                } else if constexpr (MODE == 1) {
                    int p = 4 * (cg & 511) + (cg >> 9);
                    g_a1f[l][afidx(row, p)] = tftrunc(v);
                } else if constexpr (MODE == 2) {
                    g_a2f[l][afidx(row, cg)] = tftrunc(fmaxf(v, 0.0f));
                } else {
                    float val = __ldcg(&g_hgru[l][row][cg]) * sigmoidf_(v);
                    g_hbuf[t & 1][l][row][cg] = val;
                    g_hbf[t & 1][l][afidx(row, cg)] = tftrunc(val);
                    if (l == Lq - 1)
                        outp[((size_t)row * Sq + t) * Hq + cg] = val;
                }
            }
    }
    __syncthreads();
}

// ---------------- the single persistent kernel ----------------
__global__ void __launch_bounds__(NTHR, 1) fss_persist_kernel(
    const float* __restrict__ x, const float* __restrict__ h0,
    const float* __restrict__ Wih, const float* __restrict__ Whh,
    const float* __restrict__ bih, const float* __restrict__ bhh,
    const float* __restrict__ aw0, const float* __restrict__ aw1,
    const float* __restrict__ aw2, const float* __restrict__ aw3,
    float* __restrict__ outp, int out_size)
{
    extern __shared__ float dyn[];
    const int bx = blockIdx.x, tid = threadIdx.x;
    const int gid = bx * NTHR + tid, gsz = NCTA * NTHR;

    // reset elastic counters (visible after init gridbar)
    if (gid < Lq) { g_done_t[gid] = -1; g_grudone_t[gid] = -1; }

    // --- one-time-per-launch permutes (fragment-major, tf32 pre-rounded) ---
    for (int l0 = 0; l0 < Lq; l0++) {
        permW(g_wihf + (size_t)l0 * H3q * Hq, Wih + (size_t)l0 * H3q * Hq, H3q, Hq, gid, gsz);
        permW(g_whhf + (size_t)l0 * H3q * Hq, Whh + (size_t)l0 * H3q * Hq, H3q, Hq, gid, gsz);
        permW(g_w0f + (size_t)l0 * Hq * Hq,   aw0 + (size_t)l0 * Hq * Hq,  Hq, Hq, gid, gsz);
        permW(g_w1f + (size_t)l0 * 512 * 512, aw1 + (size_t)l0 * 512 * 512, 512, 512, gid, gsz);
        permW(g_w2f + (size_t)l0 * 512 * 512, aw2 + (size_t)l0 * 512 * 512, 512, 512, gid, gsz);
        permW(g_w3f + (size_t)l0 * Hq * H2q,  aw3 + (size_t)l0 * Hq * H2q, Hq, H2q, gid, gsz);
    }
    // x -> per-timestep fragment layout
    for (size_t i = gid; i < (size_t)Sq * 65536; i += gsz) {
        int j = (int)(i & 65535);
        int t = (int)(i >> 16);
        int s = j & 3, lane = (j >> 2) & 31, mb = (j >> 7) & 3, kb = j >> 9;
        int row = mb * 16 + (lane >> 2) + ((s & 1) << 3);
        int col = kb * 8 + (lane & 3) + ((s >> 1) << 2);
        g_xf[i] = tftrunc(__ldg(x + ((size_t)row * Sq + t) * Hq + col));
    }
    // h0 -> parity-1 buffers (linear + fragment); t=0 reads parity 1
    for (int i = gid; i < Lq * 65536; i += gsz) {
        int l0 = i >> 16, j = i & 65535;
        int b = j >> 10, k = j & (Hq - 1);
        g_hbuf[1][l0][b][k] = h0[l0 * Hq + k];
        int s = j & 3, lane = (j >> 2) & 31, kb = j >> 9;
        int col = kb * 8 + (lane & 3) + ((s >> 1) << 2);
        g_hbf[1][l0][j] = tftrunc(h0[l0 * Hq + col]);
    }
    gridbar();

    const int l = bx >> 5, idx = bx & 31;
    for (int t = 0; t < Sq; ++t) {
        // input ready: layer l-1 finished its timestep t
        if (l > 0) waitge(&g_done_t[l - 1], t);
        gru_stage(dyn, l, t, idx * 32, bih, bhh);
        layerbar(l);
        if (idx == 0 && tid == 0) g_grudone_t[l] = t;   // h[l-1] parity buffer consumed
        sort_rows(dyn, l, idx);
        layerbar(l);
        fc_stage<0>(dyn, l, t, idx * 64, outp);
        layerbar(l);
        fc_stage<1>(dyn, l, t, idx * 64, outp);
        layerbar(l);
        fc_stage<2>(dyn, l, t, idx * 64, outp);
        layerbar(l);
        // fc3 overwrites parity t&1 (= our t-2 output), last read by layer l+1's GRU at its t-2
        if (l < Lq - 1) waitge(&g_grudone_t[l + 1], t - 2);
        fc_stage<3>(dyn, l, t, idx * 32, outp);
        layerbar(l);
        if (idx == 0 && tid == 0) g_done_t[l] = t;
    }
    gridbar();

    // final hidden state hT (t=255 -> parity 1), layout (L,B,H)
    if (out_size >= Bq * Sq * Hq + Lq * Bq * Hq) {
        for (int i = gid; i < Lq * Bq * Hq; i += gsz)
            outp[(size_t)Bq * Sq * Hq + i] = __ldcg(&(&g_hbuf[1][0][0][0])[i]);
    }
}

// ---------------- launch ----------------
extern "C" void kernel_launch(void* const* d_in, const int* in_sizes, int n_in,
                              void* d_out, int out_size) {
    (void)in_sizes; (void)n_in;
    cudaFuncSetAttribute(fss_persist_kernel,
                         cudaFuncAttributeMaxDynamicSharedMemorySize, SMEM_BYTES);
    fss_persist_kernel<<<NCTA, NTHR, SMEM_BYTES>>>(
        (const float*)d_in[0], (const float*)d_in[1],
        (const float*)d_in[2], (const float*)d_in[3],
        (const float*)d_in[4], (const float*)d_in[5],
        (const float*)d_in[6], (const float*)d_in[7],
        (const float*)d_in[8], (const float*)d_in[9],
        (float*)d_out, out_size);
}

// round 13
// speedup vs baseline: 1.0818x; 1.0622x over previous
#include <cuda_runtime.h>
#include <cstdint>
#include <cstddef>

#define Bq 64
#define Sq 256
#define Hq 1024
#define Lq 4
#define H2q 2048
#define H3q 3072
#define NCTA 128
#define NTHR 512
#define NPH (Sq + Lq - 1)
#define GA 4096                       // A floats per chunk (64 rows x 64 k)
#define GB 6144                       // GRU B floats per chunk (96 rows x 64 k)
#define GSTG (GA + GB)                // floats per pipeline stage
#define SMEM_BYTES (4 * GSTG * 4)     // 163840 B

// ---------------- persistent device scratch ----------------
__device__ __align__(16) float g_hbuf[2][Lq][Bq][Hq];   // fp32 state (elementwise)
__device__ __align__(16) float g_hbf[2][Lq][Bq * Hq];   // tf32 fragment copy (GEMM A)
__device__ __align__(16) float g_hgru[Lq][Bq][Hq];      // fp32 GRU out (sort + gates)
__device__ __align__(16) float g_hgf[Lq][Bq * Hq];      // fragment copy (fc0 A)
__device__ __align__(16) float g_sf[Lq][Bq * Hq];       // sorted, fragment
__device__ __align__(16) float g_a0f[Lq][Bq * H2q];     // a0 shuffled, fragment
__device__ __align__(16) float g_a1f[Lq][Bq * H2q];     // a1 shuffled, fragment
__device__ __align__(16) float g_a2f[Lq][Bq * H2q];     // relu(a2), fragment
__device__ __align__(16) float g_xf[Sq * Bq * Hq];      // x, fragment per t
// fragment-major tf32 weights
__device__ __align__(16) float g_wihf[Lq * H3q * Hq];
__device__ __align__(16) float g_whhf[Lq * H3q * Hq];
__device__ __align__(16) float g_w0f[Lq * Hq * Hq];
__device__ __align__(16) float g_w1f[Lq * 512 * 512];
__device__ __align__(16) float g_w2f[Lq * 512 * 512];
__device__ __align__(16) float g_w3f[Lq * Hq * H2q];

__device__ unsigned g_cnt = 0;
__device__ volatile unsigned g_gen = 0;
__device__ unsigned g_lcnt[Lq] = {0, 0, 0, 0};
__device__ volatile unsigned g_lgen[Lq] = {0, 0, 0, 0};

// ---------------- helpers ----------------
__device__ __forceinline__ uint32_t f2tf(float f) {
    uint32_t u;
    asm("cvt.rna.tf32.f32 %0, %1;" : "=r"(u) : "f"(f));
    return u;
}
__device__ __forceinline__ float tftrunc(float f) { return __uint_as_float(f2tf(f)); }
__device__ __forceinline__ void mma8(float* c, uint32_t a0, uint32_t a1, uint32_t a2, uint32_t a3,
                                     uint32_t b0, uint32_t b1) {
    asm volatile(
        "mma.sync.aligned.m16n8k8.row.col.f32.tf32.tf32.f32 "
        "{%0,%1,%2,%3},{%4,%5,%6,%7},{%8,%9},{%0,%1,%2,%3};"
        : "+f"(c[0]), "+f"(c[1]), "+f"(c[2]), "+f"(c[3])
        : "r"(a0), "r"(a1), "r"(a2), "r"(a3), "r"(b0), "r"(b1));
}
__device__ __forceinline__ float sigmoidf_(float x) { return 1.0f / (1.0f + __expf(-x)); }

__device__ __forceinline__ void cpa16(void* dst, const void* src) {
    uint32_t d = (uint32_t)__cvta_generic_to_shared(dst);
    asm volatile("cp.async.cg.shared.global [%0], [%1], 16;" :: "r"(d), "l"(src));
}
#define CP_COMMIT() asm volatile("cp.async.commit_group;")
__device__ __forceinline__ void cpwait(int left) {
    if (left >= 2)      asm volatile("cp.async.wait_group 2;");
    else if (left == 1) asm volatile("cp.async.wait_group 1;");
    else                asm volatile("cp.async.wait_group 0;");
}

// fragment index for 64-row A tensors: [kb=col>>3][mb4=row>>4][lane32][slot4]
__device__ __forceinline__ int afidx(int row, int col) {
    return ((((col >> 3) << 2) + (row >> 4)) * 32 + ((row & 7) * 4 + (col & 3))) * 4
         + ((((col & 7) >> 2) << 1) + ((row & 15) >> 3));
}

// ---------------- barriers ----------------
__device__ __forceinline__ void gridbar() {
    __threadfence();
    __syncthreads();
    if (threadIdx.x == 0) {
        unsigned gen = g_gen;
        if (atomicAdd(&g_cnt, 1u) == NCTA - 1) {
            g_cnt = 0;
            __threadfence();
            g_gen = gen + 1;
        } else {
            while (g_gen == gen) __nanosleep(64);
        }
    }
    __syncthreads();
}
__device__ __forceinline__ void layerbar(int l) {
    __threadfence();
    __syncthreads();
    if (threadIdx.x == 0) {
        unsigned gen = g_lgen[l];
        if (atomicAdd(&g_lcnt[l], 1u) == 31) {
            g_lcnt[l] = 0;
            __threadfence();
            g_lgen[l] = gen + 1;
        } else {
            while (g_lgen[l] == gen) __nanosleep(32);
        }
    }
    __syncthreads();
}

// ---------------- weight permute: row-major [N][K] -> fragment-major ----------------
__device__ __forceinline__ void permW(float* dst, const float* src, int N, int K,
                                      int gid, int gsz) {
    const int NB = N >> 3;
    const size_t tot = (size_t)N * K;
    for (size_t i = gid; i < tot; i += gsz) {
        int s = (int)(i & 3);
        int lane = (int)((i >> 2) & 31);
        int kb2 = (int)((i >> 7) & 3);
        size_t hi = i >> 9;
        int nb = (int)(hi % NB);
        int c = (int)(hi / NB);
        int r = nb * 8 + (lane >> 2);
        int k = c * 64 + kb2 * 16 + ((s >> 1) << 3) + ((s & 1) << 2) + (lane & 3);
        dst[i] = tftrunc(__ldg(src + (size_t)r * K + k));
    }
}

// one K64-chunk of m16n32 mma work for one warp (R9 GRU engine, 16-float acc)
#define FRAG_CHUNK(APTR, BPTR, MB, ACC) { \
    const float* A_ = (APTR); \
    const uint4* Bf_ = (const uint4*)(BPTR); \
    _Pragma("unroll") \
    for (int kb2 = 0; kb2 < 4; kb2++) { \
        uint4 b0_ = Bf_[(0 * 4 + kb2) * 32 + lane]; \
        uint4 b1_ = Bf_[(1 * 4 + kb2) * 32 + lane]; \
        uint4 b2_ = Bf_[(2 * 4 + kb2) * 32 + lane]; \
        uint4 b3_ = Bf_[(3 * 4 + kb2) * 32 + lane]; \
        _Pragma("unroll") \
        for (int pp = 0; pp < 2; pp++) { \
            uint4 aq = *(const uint4*)(A_ + ((kb2 * 2 + pp) * 4 + (MB)) * 128 + lane * 4); \
            mma8(ACC[0], aq.x, aq.y, aq.z, aq.w, pp ? b0_.z : b0_.x, pp ? b0_.w : b0_.y); \
            mma8(ACC[1], aq.x, aq.y, aq.z, aq.w, pp ? b1_.z : b1_.x, pp ? b1_.w : b1_.y); \
            mma8(ACC[2], aq.x, aq.y, aq.z, aq.w, pp ? b2_.z : b2_.x, pp ? b2_.w : b2_.y); \
            mma8(ACC[3], aq.x, aq.y, aq.z, aq.w, pp ? b3_.z : b3_.x, pp ? b3_.w : b3_.y); \
        } \
    } \
}

// m32n32 warp tile over kb2 range [KB2B, KB2B+KCNT): rows MB*32..+32 (32-float acc)
#define FRAG_T(APTR, BPTR, NBB, KB2B, KCNT, MB, ACC) { \
    const float* A_ = (APTR); \
    const uint4* Bf_ = (const uint4*)(BPTR); \
    _Pragma("unroll") \
    for (int kq = 0; kq < (KCNT); kq++) { \
        const int kb2_ = (KB2B) + kq; \
        uint4 b0_ = Bf_[(((NBB) + 0) * 4 + kb2_) * 32 + lane]; \
        uint4 b1_ = Bf_[(((NBB) + 1) * 4 + kb2_) * 32 + lane]; \
        uint4 b2_ = Bf_[(((NBB) + 2) * 4 + kb2_) * 32 + lane]; \
        uint4 b3_ = Bf_[(((NBB) + 3) * 4 + kb2_) * 32 + lane]; \
        _Pragma("unroll") \
        for (int pp = 0; pp < 2; pp++) { \
            _Pragma("unroll") \
            for (int mt = 0; mt < 2; mt++) { \
                uint4 aq = *(const uint4*)(A_ + ((kb2_ * 2 + pp) * 4 + (MB) * 2 + mt) * 128 + lane * 4); \
                mma8(ACC[mt][0], aq.x, aq.y, aq.z, aq.w, pp ? b0_.z : b0_.x, pp ? b0_.w : b0_.y); \
                mma8(ACC[mt][1], aq.x, aq.y, aq.z, aq.w, pp ? b1_.z : b1_.x, pp ? b1_.w : b1_.y); \
                mma8(ACC[mt][2], aq.x, aq.y, aq.z, aq.w, pp ? b2_.z : b2_.x, pp ? b2_.w : b2_.y); \
                mma8(ACC[mt][3], aq.x, aq.y, aq.z, aq.w, pp ? b3_.z : b3_.x, pp ? b3_.w : b3_.y); \
            } \
        } \
    } \
}

// ---------------- GRU stage: 32 H-cols/CTA, 12 compute warps (3 streams x 4 m16) ---
// (verbatim from R9 — known-good register profile)
__device__ __forceinline__ void gru_stage(float* dyn, int l, int t, int n0,
    const float* __restrict__ bih, const float* __restrict__ bhh)
{
    const int par = t & 1;
    const int tid = threadIdx.x;
    const int warp = tid >> 5, lane = tid & 31;
    const int st = warp >> 2, wm = warp & 3;     // stream, m16 block (warp<12)
    const int grp = lane >> 2, tig = lane & 3;

    const float* Af1 = (l == 0) ? (g_xf + (size_t)t * 65536) : g_hbf[par][l - 1];
    const float* Af2 = g_hbf[par ^ 1][l];
    const float* Wih_ = g_wihf + (size_t)l * H3q * Hq;
    const float* Whh_ = g_whhf + (size_t)l * H3q * Hq;

    auto issue = [&](int c, int sg) {
        float* A = dyn + sg * GSTG;
        float* B = A + GA;
        const float* as = (c < 16) ? (Af1 + (size_t)c * 4096)
                                   : (Af2 + (size_t)(c - 16) * 4096);
        cpa16(A + tid * 4, as + tid * 4);
        cpa16(A + (tid + 512) * 4, as + (tid + 512) * 4);
        const float* wmat = (c < 16) ? Wih_ : Whh_;
        const int cc = c & 15;
#pragma unroll
        for (int s3 = 0; s3 < 3; s3++) {
            const float* ws = wmat + ((size_t)(cc * 384 + s3 * 128 + (n0 >> 3))) * 512;
            cpa16(B + s3 * 2048 + tid * 4, ws + tid * 4);
        }
        CP_COMMIT();
    };

    float acc1[4][4] = {};    // R/Z full, or N(ih) for stream 2
    float acc2[4][4] = {};    // N(hh) for stream 2

    issue(0, 0); issue(1, 1); issue(2, 2);
    for (int c = 0; c < 16; c++) {
        cpwait(31 - c);
        __syncthreads();
        issue(c + 3, (c + 3) & 3);
        if (warp < 12) {
            const int sg = c & 3;
            FRAG_CHUNK(dyn + sg * GSTG, dyn + sg * GSTG + GA + st * 2048, wm, acc1);
        }
    }
    for (int c = 16; c < 32; c++) {
        cpwait(31 - c);
        __syncthreads();
        if (c + 3 < 32) issue(c + 3, (c + 3) & 3);
        if (warp < 12) {
            const int sg = c & 3;
            if (st == 2) {
                FRAG_CHUNK(dyn + sg * GSTG, dyn + sg * GSTG + GA + st * 2048, wm, acc2);
            } else {
                FRAG_CHUNK(dyn + sg * GSTG, dyn + sg * GSTG + GA + st * 2048, wm, acc1);
            }
        }
    }
    __syncthreads();

    // stage accumulators (R,Z,Ni,Nh), then combine gates
    float (*E)[64][32] = (float(*)[64][32])dyn;
    if (warp < 12) {
#pragma unroll
        for (int ns = 0; ns < 4; ns++)
#pragma unroll
            for (int e = 0; e < 4; e++) {
                int row = wm * 16 + grp + ((e >> 1) << 3);
                int col = ns * 8 + tig * 2 + (e & 1);
                if (st < 2) E[st][row][col] = acc1[ns][e];
                else { E[2][row][col] = acc1[ns][e]; E[3][row][col] = acc2[ns][e]; }
            }
    }
    __syncthreads();

    const float* bi = bih + l * H3q;
    const float* bh = bhh + l * H3q;
#pragma unroll
    for (int e = 0; e < 4; e++) {
        int q = tid + e * 512;
        int m = q >> 5, n = q & 31, col = n0 + n;
        float r  = sigmoidf_(E[0][m][n] + __ldg(bi + col) + __ldg(bh + col));
        float z  = sigmoidf_(E[1][m][n] + __ldg(bi + Hq + col) + __ldg(bh + Hq + col));
        float nn = tanhf(E[2][m][n] + __ldg(bi + 2 * Hq + col)
                         + r * (E[3][m][n] + __ldg(bh + 2 * Hq + col)));
        float hp = __ldcg(&g_hbuf[par ^ 1][l][m][col]);
        float hv = (1.0f - z) * nn + z * hp;
        g_hgru[l][m][col] = hv;
        g_hgf[l][afidx(m, col)] = tftrunc(hv);
    }
    __syncthreads();
}

// ---------------- 2-rows-per-CTA bitonic sort (ascending, 1024 each) ------------
__device__ __forceinline__ void sort_rows(float* dyn, int l, int pair) {
    const int tid = threadIdx.x;
    const int sub = tid >> 8, tt = tid & 255;
    const int b = pair * 2 + sub;
    float* s = dyn + sub * 1024;
#pragma unroll
    for (int e = 0; e < 4; e++) s[tt + (e << 8)] = __ldcg(&g_hgru[l][b][tt + (e << 8)]);
    __syncthreads();
    for (int k = 2; k <= 1024; k <<= 1) {
        for (int j = k >> 1; j > 0; j >>= 1) {
#pragma unroll
            for (int e = 0; e < 2; e++) {
                int tc = tt + (e << 8);
                int pos = ((tc & ~(j - 1)) << 1) | (tc & (j - 1));
                int q = pos | j;
                bool up = ((pos & k) == 0);
                float a = s[pos], bb = s[q];
                if ((a > bb) == up) { s[pos] = bb; s[q] = a; }
            }
            __syncthreads();
        }
    }
#pragma unroll
    for (int e = 0; e < 4; e++) {
        int pos = tt + (e << 8);
        g_sf[l][afidx(b, pos)] = tftrunc(s[pos]);
    }
    __syncthreads();
}

// ---------------- generic FC stage (8 compute warps, m32n32 K-split) ----------------
// MODE 0: a0 = [h|sorted]@w0^T (K=1024, NT=64) -> stored shuffled
// MODE 1: a1 = a0s@w1^T        (K=512,  NT=64) -> stored shuffled
// MODE 2: a2 = relu(a1s@w2^T)  (K=512,  NT=64) -> linear
// MODE 3: h' = hgru*sigmoid(a2@w3^T) (K=2048, NT=32) -> hbuf + outs(l==3)
template <int MODE>
__device__ __forceinline__ void fc_stage(float* dyn, int l, int t, int n0,
                                         float* __restrict__ outp)
{
    constexpr int NCH = (MODE == 0) ? 16 : (MODE == 3 ? 32 : 8);
    constexpr int BFL = (MODE == 3) ? 2048 : 4096;
    constexpr int KCNT = (MODE == 3) ? 1 : 2;    // kb2 per warp per chunk

    const int tid = threadIdx.x;
    const int warp = tid >> 5, lane = tid & 31;
    const int grp = lane >> 2, tig = lane & 3;
    // warp mapping (warp < 8): m32 block, n32 block, k-split
    const int mb  = warp & 1;
    const int nbw = (MODE == 3) ? 0 : ((warp >> 1) & 1);
    const int ks  = (MODE == 3) ? (warp >> 1) : ((warp >> 2) & 1);

    const float* Af;
    if constexpr (MODE == 0)      Af = (n0 >= Hq) ? g_sf[l] : g_hgf[l];
    else if constexpr (MODE == 1) Af = g_a0f[l] + ((size_t)(n0 >> 9) << 15);
    else if constexpr (MODE == 2) Af = g_a1f[l] + ((size_t)(n0 >> 9) << 15);
    else                          Af = g_a2f[l];

    const float* Wf; int o0; int NBALL;
    if constexpr (MODE == 0)      { Wf = g_w0f + (size_t)l * Hq * Hq;   o0 = n0 & (Hq - 1); NBALL = 128; }
    else if constexpr (MODE == 1) { Wf = g_w1f + (size_t)l * 512 * 512; o0 = n0 & 511;      NBALL = 64; }
    else if constexpr (MODE == 2) { Wf = g_w2f + (size_t)l * 512 * 512; o0 = n0 & 511;      NBALL = 64; }
    else                          { Wf = g_w3f + (size_t)l * Hq * H2q;  o0 = n0;            NBALL = 128; }

    auto issue = [&](int c, int sg) {
        float* A = dyn + sg * GSTG;
        float* B = A + GA;
        const float* as = Af + (size_t)c * 4096;
        cpa16(A + tid * 4, as + tid * 4);
        cpa16(A + (tid + 512) * 4, as + (tid + 512) * 4);
        const float* ws = Wf + ((size_t)c * NBALL + (o0 >> 3)) * 512;
        cpa16(B + tid * 4, ws + tid * 4);
        if (BFL == 4096) cpa16(B + (tid + 512) * 4, ws + (tid + 512) * 4);
        CP_COMMIT();
    };

    float acc[2][4][4] = {};     // 32 floats: m32 x n32

    issue(0, 0); issue(1, 1); issue(2, 2);
    for (int c = 0; c < NCH; c++) {
        cpwait(NCH - 1 - c);
        __syncthreads();
        if (c + 3 < NCH) issue(c + 3, (c + 3) & 3);
        if (warp < 8) {
            const int sg = c & 3;
            FRAG_T(dyn + sg * GSTG, dyn + sg * GSTG + GA, nbw * 4, ks * KCNT, KCNT, mb, acc);
        }
    }
    __syncthreads();

    // stage K-split partials in smem (pipeline drained -> dyn free), combine, write
    if constexpr (MODE == 3) {
        float (*Epi)[64][32] = (float(*)[64][32])dyn;   // [ks4][64][32] = 32 KB
        if (warp < 8) {
#pragma unroll
            for (int mt = 0; mt < 2; mt++)
#pragma unroll
                for (int ns = 0; ns < 4; ns++)
#pragma unroll
                    for (int e = 0; e < 4; e++) {
                        int row = mb * 32 + mt * 16 + grp + ((e >> 1) << 3);
                        int col = ns * 8 + tig * 2 + (e & 1);
                        Epi[ks][row][col] = acc[mt][ns][e];
                    }
        }
        __syncthreads();
#pragma unroll
        for (int i = 0; i < 4; i++) {
            int q = tid + i * 512;
            int row = q >> 5, col = q & 31, cg = n0 + col;
            float v = Epi[0][row][col] + Epi[1][row][col] + Epi[2][row][col] + Epi[3][row][col];
            float val = __ldcg(&g_hgru[l][row][cg]) * sigmoidf_(v);
            g_hbuf[t & 1][l][row][cg] = val;
            g_hbf[t & 1][l][afidx(row, cg)] = tftrunc(val);
            if (l == Lq - 1)
                outp[((size_t)row * Sq + t) * Hq + cg] = val;
        }
    } else {
        float (*Epi)[64][64] = (float(*)[64][64])dyn;   // [ks2][64][64] = 32 KB
        if (warp < 8) {
#pragma unroll
            for (int mt = 0; mt < 2; mt++)
#pragma unroll
                for (int ns = 0; ns < 4; ns++)
#pragma unroll
                    for (int e = 0; e < 4; e++) {
                        int row = mb * 32 + mt * 16 + grp + ((e >> 1) << 3);
                        int col = nbw * 32 + ns * 8 + tig * 2 + (e & 1);
                        Epi[ks][row][col] = acc[mt][ns][e];
                    }
        }
        __syncthreads();
#pragma unroll
        for (int i = 0; i < 8; i++) {
            int q = tid + i * 512;
            int row = q >> 6, col = q & 63, cg = n0 + col;
            float v = Epi[0][row][col] + Epi[1][row][col];
            if constexpr (MODE == 0) {
                int p = 4 * (cg & 511) + (cg >> 9);
                g_a0f[l][afidx(row, p)] = tftrunc(v);
            } else if constexpr (MODE == 1) {
                int p = 4 * (cg & 511) + (cg >> 9);
                g_a1f[l][afidx(row, p)] = tftrunc(v);
            } else {
                g_a2f[l][afidx(row, cg)] = tftrunc(fmaxf(v, 0.0f));
            }
        }
    }
    __syncthreads();
}

// ---------------- the single persistent kernel ----------------
__global__ void __launch_bounds__(NTHR, 1) fss_persist_kernel(
    const float* __restrict__ x, const float* __restrict__ h0,
    const float* __restrict__ Wih, const float* __restrict__ Whh,
    const float* __restrict__ bih, const float* __restrict__ bhh,
    const float* __restrict__ aw0, const float* __restrict__ aw1,
    const float* __restrict__ aw2, const float* __restrict__ aw3,
    float* __restrict__ outp, int out_size)
{
    extern __shared__ float dyn[];
    const int bx = blockIdx.x, tid = threadIdx.x;
    const int gid = bx * NTHR + tid, gsz = NCTA * NTHR;

    // --- one-time-per-launch permutes (fragment-major, tf32 pre-rounded) ---
    for (int l0 = 0; l0 < Lq; l0++) {
        permW(g_wihf + (size_t)l0 * H3q * Hq, Wih + (size_t)l0 * H3q * Hq, H3q, Hq, gid, gsz);
        permW(g_whhf + (size_t)l0 * H3q * Hq, Whh + (size_t)l0 * H3q * Hq, H3q, Hq, gid, gsz);
        permW(g_w0f + (size_t)l0 * Hq * Hq,   aw0 + (size_t)l0 * Hq * Hq,  Hq, Hq, gid, gsz);
        permW(g_w1f + (size_t)l0 * 512 * 512, aw1 + (size_t)l0 * 512 * 512, 512, 512, gid, gsz);
        permW(g_w2f + (size_t)l0 * 512 * 512, aw2 + (size_t)l0 * 512 * 512, 512, 512, gid, gsz);
        permW(g_w3f + (size_t)l0 * Hq * H2q,  aw3 + (size_t)l0 * Hq * H2q, Hq, H2q, gid, gsz);
    }
    // x -> per-timestep fragment layout
    for (size_t i = gid; i < (size_t)Sq * 65536; i += gsz) {
        int j = (int)(i & 65535);
        int t = (int)(i >> 16);
        int s = j & 3, lane = (j >> 2) & 31, mb = (j >> 7) & 3, kb = j >> 9;
        int row = mb * 16 + (lane >> 2) + ((s & 1) << 3);
        int col = kb * 8 + (lane & 3) + ((s >> 1) << 2);
        g_xf[i] = tftrunc(__ldg(x + ((size_t)row * Sq + t) * Hq + col));
    }
    // h0 -> parity-1 buffers (linear + fragment); t=0 reads parity 1
    for (int i = gid; i < Lq * 65536; i += gsz) {
        int l0 = i >> 16, j = i & 65535;
        int b = j >> 10, k = j & (Hq - 1);
        g_hbuf[1][l0][b][k] = h0[l0 * Hq + k];
        int s = j & 3, lane = (j >> 2) & 31, kb = j >> 9;
        int col = kb * 8 + (lane & 3) + ((s >> 1) << 2);
        g_hbf[1][l0][j] = tftrunc(h0[l0 * Hq + col]);
    }
    gridbar();

    const int l = bx >> 5, idx = bx & 31;
    for (int p = 0; p < NPH; ++p) {
        const int t = p - l;
        if (t >= 0 && t < Sq) {
            gru_stage(dyn, l, t, idx * 32, bih, bhh);
            layerbar(l);
            sort_rows(dyn, l, idx);
            layerbar(l);
            fc_stage<0>(dyn, l, t, idx * 64, outp);
            layerbar(l);
            fc_stage<1>(dyn, l, t, idx * 64, outp);
            layerbar(l);
            fc_stage<2>(dyn, l, t, idx * 64, outp);
            layerbar(l);
            fc_stage<3>(dyn, l, t, idx * 32, outp);
        }
        gridbar();
    }

    // final hidden state hT (t=255 -> parity 1), layout (L,B,H)
    if (out_size >= Bq * Sq * Hq + Lq * Bq * Hq) {
        for (int i = gid; i < Lq * Bq * Hq; i += gsz)
            outp[(size_t)Bq * Sq * Hq + i] = __ldcg(&(&g_hbuf[1][0][0][0])[i]);
    }
}

// ---------------- launch ----------------
extern "C" void kernel_launch(void* const* d_in, const int* in_sizes, int n_in,
                              void* d_out, int out_size) {
    (void)in_sizes; (void)n_in;
    cudaFuncSetAttribute(fss_persist_kernel,
                         cudaFuncAttributeMaxDynamicSharedMemorySize, SMEM_BYTES);
    fss_persist_kernel<<<NCTA, NTHR, SMEM_BYTES>>>(
        (const float*)d_in[0], (const float*)d_in[1],
        (const float*)d_in[2], (const float*)d_in[3],
        (const float*)d_in[4], (const float*)d_in[5],
        (const float*)d_in[6], (const float*)d_in[7],
        (const float*)d_in[8], (const float*)d_in[9],
        (float*)d_out, out_size);
}

// round 14
// speedup vs baseline: 1.2990x; 1.2008x over previous
#include <cuda_runtime.h>
#include <cstdint>
#include <cstddef>

#define Bq 64
#define Sq 256
#define Hq 1024
#define Lq 4
#define H2q 2048
#define H3q 3072
#define NCTA 128
#define NTHR 512
#define NPH (Sq + Lq - 1)
#define GA 4096                       // A floats per chunk (64 rows x 64 k)
#define GB 6144                       // GRU B floats per chunk (96 rows x 64 k)
#define GSTG (GA + GB)                // floats per pipeline stage slot
#define SMEM_BYTES (4 * GSTG * 4)     // 163840 B

// ---------------- persistent device scratch ----------------
__device__ __align__(16) float g_hbuf[2][Lq][Bq][Hq];   // fp32 state (elementwise)
__device__ __align__(16) float g_hbf[2][Lq][Bq * Hq];   // tf32 fragment copy (GEMM A)
__device__ __align__(16) float g_hgru[Lq][Bq][Hq];      // fp32 GRU out (sort + gates)
__device__ __align__(16) float g_hgf[Lq][Bq * Hq];      // fragment copy (fc0 A)
__device__ __align__(16) float g_sf[Lq][Bq * Hq];       // sorted, fragment
__device__ __align__(16) float g_a0f[Lq][Bq * H2q];     // a0 shuffled, fragment
__device__ __align__(16) float g_a1f[Lq][Bq * H2q];     // a1 shuffled, fragment
__device__ __align__(16) float g_a2f[Lq][Bq * H2q];     // relu(a2), fragment
__device__ __align__(16) float g_xf[Sq * Bq * Hq];      // x, fragment per t
// fragment-major tf32 weights
__device__ __align__(16) float g_wihf[Lq * H3q * Hq];
__device__ __align__(16) float g_whhf[Lq * H3q * Hq];
__device__ __align__(16) float g_w0f[Lq * Hq * Hq];
__device__ __align__(16) float g_w1f[Lq * 512 * 512];
__device__ __align__(16) float g_w2f[Lq * 512 * 512];
__device__ __align__(16) float g_w3f[Lq * Hq * H2q];

__device__ unsigned g_cnt = 0;
__device__ volatile unsigned g_gen = 0;
__device__ unsigned g_lcnt[Lq] = {0, 0, 0, 0};
__device__ volatile unsigned g_lgen[Lq] = {0, 0, 0, 0};

// ---------------- helpers ----------------
__device__ __forceinline__ uint32_t f2tf(float f) {
    uint32_t u;
    asm("cvt.rna.tf32.f32 %0, %1;" : "=r"(u) : "f"(f));
    return u;
}
__device__ __forceinline__ float tftrunc(float f) { return __uint_as_float(f2tf(f)); }
__device__ __forceinline__ void mma8(float* c, uint32_t a0, uint32_t a1, uint32_t a2, uint32_t a3,
                                     uint32_t b0, uint32_t b1) {
    asm volatile(
        "mma.sync.aligned.m16n8k8.row.col.f32.tf32.tf32.f32 "
        "{%0,%1,%2,%3},{%4,%5,%6,%7},{%8,%9},{%0,%1,%2,%3};"
        : "+f"(c[0]), "+f"(c[1]), "+f"(c[2]), "+f"(c[3])
        : "r"(a0), "r"(a1), "r"(a2), "r"(a3), "r"(b0), "r"(b1));
}
__device__ __forceinline__ float sigmoidf_(float x) { return 1.0f / (1.0f + __expf(-x)); }

// ---------------- TMA bulk + mbarrier primitives ----------------
__device__ __forceinline__ void tbulk(uint32_t dst, const void* src, uint32_t bytes, uint32_t mbar) {
    asm volatile(
        "cp.async.bulk.shared::cluster.global.mbarrier::complete_tx::bytes [%0], [%1], %2, [%3];"
        :: "r"(dst), "l"(src), "r"(bytes), "r"(mbar) : "memory");
}
#define MBI(addr, cnt) asm volatile("mbarrier.init.shared.b64 [%0], %1;" :: "r"(addr), "r"(cnt) : "memory")
#define MBEXP(addr, tx) asm volatile("mbarrier.arrive.expect_tx.shared.b64 _, [%0], %1;" :: "r"(addr), "r"(tx) : "memory")
#define MBARR(addr) asm volatile("mbarrier.arrive.shared.b64 _, [%0];" :: "r"(addr) : "memory")
#define FENCE_PA() asm volatile("fence.proxy.async.shared::cta;" ::: "memory")

__device__ __forceinline__ void mb_wait(uint32_t mbar, uint32_t parity) {
    uint32_t done;
    asm volatile(
        "{\n\t.reg .pred p;\n\t"
        "mbarrier.try_wait.parity.acquire.cta.shared::cta.b64 p, [%1], %2;\n\t"
        "selp.b32 %0, 1, 0, p;\n\t}"
        : "=r"(done) : "r"(mbar), "r"(parity) : "memory");
    while (!done) {
        asm volatile(
            "{\n\t.reg .pred p;\n\t"
            "mbarrier.try_wait.parity.acquire.cta.shared::cta.b64 p, [%1], %2, 0x989680;\n\t"
            "selp.b32 %0, 1, 0, p;\n\t}"
            : "=r"(done) : "r"(mbar), "r"(parity) : "memory");
    }
}
// mbar layout in static smem: full[s] at mbu + s*8, empty[s] at mbu + 32 + s*8
#define MB_FULL(mbu, s)  ((mbu) + (s) * 8)
#define MB_EMPTY(mbu, s) ((mbu) + 32 + (s) * 8)
#define NCONS 15

// fragment index for 64-row A tensors: [kb=col>>3][mb4=row>>4][lane32][slot4]
__device__ __forceinline__ int afidx(int row, int col) {
    return ((((col >> 3) << 2) + (row >> 4)) * 32 + ((row & 7) * 4 + (col & 3))) * 4
         + ((((col & 7) >> 2) << 1) + ((row & 15) >> 3));
}

// ---------------- barriers ----------------
__device__ __forceinline__ void gridbar() {
    __threadfence();
    __syncthreads();
    if (threadIdx.x == 0) {
        unsigned gen = g_gen;
        if (atomicAdd(&g_cnt, 1u) == NCTA - 1) {
            g_cnt = 0;
            __threadfence();
            g_gen = gen + 1;
        } else {
            while (g_gen == gen) __nanosleep(64);
        }
    }
    __syncthreads();
}
__device__ __forceinline__ void layerbar(int l) {
    __threadfence();
    __syncthreads();
    if (threadIdx.x == 0) {
        unsigned gen = g_lgen[l];
        if (atomicAdd(&g_lcnt[l], 1u) == 31) {
            g_lcnt[l] = 0;
            __threadfence();
            g_lgen[l] = gen + 1;
        } else {
            while (g_lgen[l] == gen) __nanosleep(32);
        }
    }
    __syncthreads();
}

// ---------------- weight permute: row-major [N][K] -> fragment-major ----------------
__device__ __forceinline__ void permW(float* dst, const float* src, int N, int K,
                                      int gid, int gsz) {
    const int NB = N >> 3;
    const size_t tot = (size_t)N * K;
    for (size_t i = gid; i < tot; i += gsz) {
        int s = (int)(i & 3);
        int lane = (int)((i >> 2) & 31);
        int kb2 = (int)((i >> 7) & 3);
        size_t hi = i >> 9;
        int nb = (int)(hi % NB);
        int c = (int)(hi / NB);
        int r = nb * 8 + (lane >> 2);
        int k = c * 64 + kb2 * 16 + ((s >> 1) << 3) + ((s & 1) << 2) + (lane & 3);
        dst[i] = tftrunc(__ldg(src + (size_t)r * K + k));
    }
}

// one K64-chunk of m16n32 mma work for one warp (16-float acc)
#define FRAG_CHUNK(APTR, BPTR, MB, ACC) { \
    const float* A_ = (APTR); \
    const uint4* Bf_ = (const uint4*)(BPTR); \
    _Pragma("unroll") \
    for (int kb2 = 0; kb2 < 4; kb2++) { \
        uint4 b0_ = Bf_[(0 * 4 + kb2) * 32 + lane]; \
        uint4 b1_ = Bf_[(1 * 4 + kb2) * 32 + lane]; \
        uint4 b2_ = Bf_[(2 * 4 + kb2) * 32 + lane]; \
        uint4 b3_ = Bf_[(3 * 4 + kb2) * 32 + lane]; \
        _Pragma("unroll") \
        for (int pp = 0; pp < 2; pp++) { \
            uint4 aq = *(const uint4*)(A_ + ((kb2 * 2 + pp) * 4 + (MB)) * 128 + lane * 4); \
            mma8(ACC[0], aq.x, aq.y, aq.z, aq.w, pp ? b0_.z : b0_.x, pp ? b0_.w : b0_.y); \
            mma8(ACC[1], aq.x, aq.y, aq.z, aq.w, pp ? b1_.z : b1_.x, pp ? b1_.w : b1_.y); \
            mma8(ACC[2], aq.x, aq.y, aq.z, aq.w, pp ? b2_.z : b2_.x, pp ? b2_.w : b2_.y); \
            mma8(ACC[3], aq.x, aq.y, aq.z, aq.w, pp ? b3_.z : b3_.x, pp ? b3_.w : b3_.y); \
        } \
    } \
}

// m32n32 warp tile over kb2 range [KB2B, KB2B+KCNT): rows MB*32..+32 (32-float acc)
#define FRAG_T(APTR, BPTR, NBB, KB2B, KCNT, MB, ACC) { \
    const float* A_ = (APTR); \
    const uint4* Bf_ = (const uint4*)(BPTR); \
    _Pragma("unroll") \
    for (int kq = 0; kq < (KCNT); kq++) { \
        const int kb2_ = (KB2B) + kq; \
        uint4 b0_ = Bf_[(((NBB) + 0) * 4 + kb2_) * 32 + lane]; \
        uint4 b1_ = Bf_[(((NBB) + 1) * 4 + kb2_) * 32 + lane]; \
        uint4 b2_ = Bf_[(((NBB) + 2) * 4 + kb2_) * 32 + lane]; \
        uint4 b3_ = Bf_[(((NBB) + 3) * 4 + kb2_) * 32 + lane]; \
        _Pragma("unroll") \
        for (int pp = 0; pp < 2; pp++) { \
            _Pragma("unroll") \
            for (int mt = 0; mt < 2; mt++) { \
                uint4 aq = *(const uint4*)(A_ + ((kb2_ * 2 + pp) * 4 + (MB) * 2 + mt) * 128 + lane * 4); \
                mma8(ACC[mt][0], aq.x, aq.y, aq.z, aq.w, pp ? b0_.z : b0_.x, pp ? b0_.w : b0_.y); \
                mma8(ACC[mt][1], aq.x, aq.y, aq.z, aq.w, pp ? b1_.z : b1_.x, pp ? b1_.w : b1_.y); \
                mma8(ACC[mt][2], aq.x, aq.y, aq.z, aq.w, pp ? b2_.z : b2_.x, pp ? b2_.w : b2_.y); \
                mma8(ACC[mt][3], aq.x, aq.y, aq.z, aq.w, pp ? b3_.z : b3_.x, pp ? b3_.w : b3_.y); \
            } \
        } \
    } \
}

// ---------------- GRU stage: 32 H-cols/CTA, 12 compute warps + TMA producer -------
__device__ __forceinline__ void gru_stage(float* dyn, uint32_t dynu, uint32_t mbu, int gch,
    int l, int t, int n0,
    const float* __restrict__ bih, const float* __restrict__ bhh)
{
    const int par = t & 1;
    const int tid = threadIdx.x;
    const int warp = tid >> 5, lane = tid & 31;
    const int st = warp >> 2, wm = warp & 3;     // stream, m16 block (warp<12)
    const int grp = lane >> 2, tig = lane & 3;

    const float* Af1 = (l == 0) ? (g_xf + (size_t)t * 65536) : g_hbf[par][l - 1];
    const float* Af2 = g_hbf[par ^ 1][l];
    const float* Wih_ = g_wihf + (size_t)l * H3q * Hq;
    const float* Whh_ = g_whhf + (size_t)l * H3q * Hq;

    float acc1[4][4] = {};    // R/Z full, or N(ih) for stream 2
    float acc2[4][4] = {};    // N(hh) for stream 2

    if (warp == 15) {
        if (lane == 0) {
            for (int c = 0; c < 32; c++) {
                const int g = gch + c;
                const int s = g & 3;
                mb_wait(MB_EMPTY(mbu, s), (((g >> 2) & 1) ^ 1));
                const uint32_t fb = MB_FULL(mbu, s);
                MBEXP(fb, 40960u);
                const uint32_t da = dynu + (uint32_t)s * (GSTG * 4);
                const float* as = (c < 16) ? (Af1 + (size_t)c * 4096)
                                           : (Af2 + (size_t)(c - 16) * 4096);
                tbulk(da, as, 16384u, fb);
                const float* wmat = (c < 16) ? Wih_ : Whh_;
                const int cc = c & 15;
#pragma unroll
                for (int s3 = 0; s3 < 3; s3++)
                    tbulk(da + GA * 4 + s3 * 8192,
                          wmat + ((size_t)(cc * 384 + s3 * 128 + (n0 >> 3))) * 512,
                          8192u, fb);
            }
        }
    } else {
        for (int c = 0; c < 16; c++) {
            const int g = gch + c;
            const int s = g & 3;
            mb_wait(MB_FULL(mbu, s), (g >> 2) & 1);
            if (warp < 12) {
                FRAG_CHUNK(dyn + s * GSTG, dyn + s * GSTG + GA + st * 2048, wm, acc1);
            }
            if (lane == 0) MBARR(MB_EMPTY(mbu, s));
        }
        for (int c = 16; c < 32; c++) {
            const int g = gch + c;
            const int s = g & 3;
            mb_wait(MB_FULL(mbu, s), (g >> 2) & 1);
            if (warp < 12) {
                if (st == 2) {
                    FRAG_CHUNK(dyn + s * GSTG, dyn + s * GSTG + GA + st * 2048, wm, acc2);
                } else {
                    FRAG_CHUNK(dyn + s * GSTG, dyn + s * GSTG + GA + st * 2048, wm, acc1);
                }
            }
            if (lane == 0) MBARR(MB_EMPTY(mbu, s));
        }
    }
    __syncthreads();

    // stage accumulators (R,Z,Ni,Nh), then combine gates
    float (*E)[64][32] = (float(*)[64][32])dyn;
    if (warp < 12) {
#pragma unroll
        for (int ns = 0; ns < 4; ns++)
#pragma unroll
            for (int e = 0; e < 4; e++) {
                int row = wm * 16 + grp + ((e >> 1) << 3);
                int col = ns * 8 + tig * 2 + (e & 1);
                if (st < 2) E[st][row][col] = acc1[ns][e];
                else { E[2][row][col] = acc1[ns][e]; E[3][row][col] = acc2[ns][e]; }
            }
    }
    __syncthreads();

    const float* bi = bih + l * H3q;
    const float* bh = bhh + l * H3q;
#pragma unroll
    for (int e = 0; e < 4; e++) {
        int q = tid + e * 512;
        int m = q >> 5, n = q & 31, col = n0 + n;
        float r  = sigmoidf_(E[0][m][n] + __ldg(bi + col) + __ldg(bh + col));
        float z  = sigmoidf_(E[1][m][n] + __ldg(bi + Hq + col) + __ldg(bh + Hq + col));
        float nn = tanhf(E[2][m][n] + __ldg(bi + 2 * Hq + col)
                         + r * (E[3][m][n] + __ldg(bh + 2 * Hq + col)));
        float hp = __ldcg(&g_hbuf[par ^ 1][l][m][col]);
        float hv = (1.0f - z) * nn + z * hp;
        g_hgru[l][m][col] = hv;
        g_hgf[l][afidx(m, col)] = tftrunc(hv);
    }
    FENCE_PA();
    __syncthreads();
}

// ---------------- 2-rows-per-CTA bitonic sort (ascending, 1024 each) ------------
__device__ __forceinline__ void sort_rows(float* dyn, int l, int pair) {
    const int tid = threadIdx.x;
    const int sub = tid >> 8, tt = tid & 255;
    const int b = pair * 2 + sub;
    float* s = dyn + sub * 1024;
#pragma unroll
    for (int e = 0; e < 4; e++) s[tt + (e << 8)] = __ldcg(&g_hgru[l][b][tt + (e << 8)]);
    __syncthreads();
    for (int k = 2; k <= 1024; k <<= 1) {
        for (int j = k >> 1; j > 0; j >>= 1) {
#pragma unroll
            for (int e = 0; e < 2; e++) {
                int tc = tt + (e << 8);
                int pos = ((tc & ~(j - 1)) << 1) | (tc & (j - 1));
                int q = pos | j;
                bool up = ((pos & k) == 0);
                float a = s[pos], bb = s[q];
                if ((a > bb) == up) { s[pos] = bb; s[q] = a; }
            }
            __syncthreads();
        }
    }
#pragma unroll
    for (int e = 0; e < 4; e++) {
        int pos = tt + (e << 8);
        g_sf[l][afidx(b, pos)] = tftrunc(s[pos]);
    }
    FENCE_PA();
    __syncthreads();
}

// ---------------- generic FC stage (8 compute warps, m32n32 K-split, TMA) --------
// MODE 0: a0 = [h|sorted]@w0^T (K=1024, NT=64) -> stored shuffled
// MODE 1: a1 = a0s@w1^T        (K=512,  NT=64) -> stored shuffled
// MODE 2: a2 = relu(a1s@w2^T)  (K=512,  NT=64) -> linear
// MODE 3: h' = hgru*sigmoid(a2@w3^T) (K=2048, NT=32) -> hbuf + outs(l==3)
template <int MODE>
__device__ __forceinline__ void fc_stage(float* dyn, uint32_t dynu, uint32_t mbu, int gch,
                                         int l, int t, int n0, float* __restrict__ outp)
{
    constexpr int NCH = (MODE == 0) ? 16 : (MODE == 3 ? 32 : 8);
    constexpr int BFL = (MODE == 3) ? 2048 : 4096;
    constexpr int KCNT = (MODE == 3) ? 1 : 2;    // kb2 per warp per chunk

    const int tid = threadIdx.x;
    const int warp = tid >> 5, lane = tid & 31;
    const int grp = lane >> 2, tig = lane & 3;
    const int mb  = warp & 1;
    const int nbw = (MODE == 3) ? 0 : ((warp >> 1) & 1);
    const int ks  = (MODE == 3) ? (warp >> 1) : ((warp >> 2) & 1);

    const float* Af;
    if constexpr (MODE == 0)      Af = (n0 >= Hq) ? g_sf[l] : g_hgf[l];
    else if constexpr (MODE == 1) Af = g_a0f[l] + ((size_t)(n0 >> 9) << 15);
    else if constexpr (MODE == 2) Af = g_a1f[l] + ((size_t)(n0 >> 9) << 15);
    else                          Af = g_a2f[l];

    const float* Wf; int o0; int NBALL;
    if constexpr (MODE == 0)      { Wf = g_w0f + (size_t)l * Hq * Hq;   o0 = n0 & (Hq - 1); NBALL = 128; }
    else if constexpr (MODE == 1) { Wf = g_w1f + (size_t)l * 512 * 512; o0 = n0 & 511;      NBALL = 64; }
    else if constexpr (MODE == 2) { Wf = g_w2f + (size_t)l * 512 * 512; o0 = n0 & 511;      NBALL = 64; }
    else                          { Wf = g_w3f + (size_t)l * Hq * H2q;  o0 = n0;            NBALL = 128; }

    float acc[2][4][4] = {};     // 32 floats: m32 x n32

    if (warp == 15) {
        if (lane == 0) {
            for (int c = 0; c < NCH; c++) {
                const int g = gch + c;
                const int s = g & 3;
                mb_wait(MB_EMPTY(mbu, s), (((g >> 2) & 1) ^ 1));
                const uint32_t fb = MB_FULL(mbu, s);
                MBEXP(fb, 16384u + BFL * 4u);
                const uint32_t da = dynu + (uint32_t)s * (GSTG * 4);
                tbulk(da, Af + (size_t)c * 4096, 16384u, fb);
                tbulk(da + GA * 4, Wf + ((size_t)c * NBALL + (o0 >> 3)) * 512, BFL * 4u, fb);
            }
        }
    } else {
        for (int c = 0; c < NCH; c++) {
            const int g = gch + c;
            const int s = g & 3;
            mb_wait(MB_FULL(mbu, s), (g >> 2) & 1);
            if (warp < 8) {
                FRAG_T(dyn + s * GSTG, dyn + s * GSTG + GA, nbw * 4, ks * KCNT, KCNT, mb, acc);
            }
            if (lane == 0) MBARR(MB_EMPTY(mbu, s));
        }
    }
    __syncthreads();

    // stage K-split partials in smem, combine, write
    if constexpr (MODE == 3) {
        float (*Epi)[64][32] = (float(*)[64][32])dyn;   // [ks4][64][32] = 32 KB
        if (warp < 8) {
#pragma unroll
            for (int mt = 0; mt < 2; mt++)
#pragma unroll
                for (int ns = 0; ns < 4; ns++)
#pragma unroll
                    for (int e = 0; e < 4; e++) {
                        int row = mb * 32 + mt * 16 + grp + ((e >> 1) << 3);
                        int col = ns * 8 + tig * 2 + (e & 1);
                        Epi[ks][row][col] = acc[mt][ns][e];
                    }
        }
        __syncthreads();
#pragma unroll
        for (int i = 0; i < 4; i++) {
            int q = tid + i * 512;
            int row = q >> 5, col = q & 31, cg = n0 + col;
            float v = Epi[0][row][col] + Epi[1][row][col] + Epi[2][row][col] + Epi[3][row][col];
            float val = __ldcg(&g_hgru[l][row][cg]) * sigmoidf_(v);
            g_hbuf[t & 1][l][row][cg] = val;
            g_hbf[t & 1][l][afidx(row, cg)] = tftrunc(val);
            if (l == Lq - 1)
                outp[((size_t)row * Sq + t) * Hq + cg] = val;
        }
    } else {
        float (*Epi)[64][64] = (float(*)[64][64])dyn;   // [ks2][64][64] = 32 KB
        if (warp < 8) {
#pragma unroll
            for (int mt = 0; mt < 2; mt++)
#pragma unroll
                for (int ns = 0; ns < 4; ns++)
#pragma unroll
                    for (int e = 0; e < 4; e++) {
                        int row = mb * 32 + mt * 16 + grp + ((e >> 1) << 3);
                        int col = nbw * 32 + ns * 8 + tig * 2 + (e & 1);
                        Epi[ks][row][col] = acc[mt][ns][e];
                    }
        }
        __syncthreads();
#pragma unroll
        for (int i = 0; i < 8; i++) {
            int q = tid + i * 512;
            int row = q >> 6, col = q & 63, cg = n0 + col;
            float v = Epi[0][row][col] + Epi[1][row][col];
            if constexpr (MODE == 0) {
                int p = 4 * (cg & 511) + (cg >> 9);
                g_a0f[l][afidx(row, p)] = tftrunc(v);
            } else if constexpr (MODE == 1) {
                int p = 4 * (cg & 511) + (cg >> 9);
                g_a1f[l][afidx(row, p)] = tftrunc(v);
            } else {
                g_a2f[l][afidx(row, cg)] = tftrunc(fmaxf(v, 0.0f));
            }
        }
    }
    FENCE_PA();
    __syncthreads();
}

// ---------------- the single persistent kernel ----------------
__global__ void __launch_bounds__(NTHR, 1) fss_persist_kernel(
    const float* __restrict__ x, const float* __restrict__ h0,
    const float* __restrict__ Wih, const float* __restrict__ Whh,
    const float* __restrict__ bih, const float* __restrict__ bhh,
    const float* __restrict__ aw0, const float* __restrict__ aw1,
    const float* __restrict__ aw2, const float* __restrict__ aw3,
    float* __restrict__ outp, int out_size)
{
    extern __shared__ float dyn[];
    __shared__ __align__(16) uint64_t s_mb[8];
    const int bx = blockIdx.x, tid = threadIdx.x;
    const int gid = bx * NTHR + tid, gsz = NCTA * NTHR;
    const uint32_t dynu = (uint32_t)__cvta_generic_to_shared(dyn);
    const uint32_t mbu  = (uint32_t)__cvta_generic_to_shared(s_mb);

    // init pipeline mbarriers ONCE (full: 1 producer arrival+tx; empty: 15 warp arrivals)
    if (tid == 0) {
        for (int s = 0; s < 4; s++) {
            MBI(MB_FULL(mbu, s), 1);
            MBI(MB_EMPTY(mbu, s), NCONS);
        }
    }
    __syncthreads();

    // --- one-time-per-launch permutes (fragment-major, tf32 pre-rounded) ---
    for (int l0 = 0; l0 < Lq; l0++) {
        permW(g_wihf + (size_t)l0 * H3q * Hq, Wih + (size_t)l0 * H3q * Hq, H3q, Hq, gid, gsz);
        permW(g_whhf + (size_t)l0 * H3q * Hq, Whh + (size_t)l0 * H3q * Hq, H3q, Hq, gid, gsz);
        permW(g_w0f + (size_t)l0 * Hq * Hq,   aw0 + (size_t)l0 * Hq * Hq,  Hq, Hq, gid, gsz);
        permW(g_w1f + (size_t)l0 * 512 * 512, aw1 + (size_t)l0 * 512 * 512, 512, 512, gid, gsz);
        permW(g_w2f + (size_t)l0 * 512 * 512, aw2 + (size_t)l0 * 512 * 512, 512, 512, gid, gsz);
        permW(g_w3f + (size_t)l0 * Hq * H2q,  aw3 + (size_t)l0 * Hq * H2q, Hq, H2q, gid, gsz);
    }
    // x -> per-timestep fragment layout
    for (size_t i = gid; i < (size_t)Sq * 65536; i += gsz) {
        int j = (int)(i & 65535);
        int t = (int)(i >> 16);
        int s = j & 3, lane = (j >> 2) & 31, mb = (j >> 7) & 3, kb = j >> 9;
        int row = mb * 16 + (lane >> 2) + ((s & 1) << 3);
        int col = kb * 8 + (lane & 3) + ((s >> 1) << 2);
        g_xf[i] = tftrunc(__ldg(x + ((size_t)row * Sq + t) * Hq + col));
    }
    // h0 -> parity-1 buffers (linear + fragment); t=0 reads parity 1
    for (int i = gid; i < Lq * 65536; i += gsz) {
        int l0 = i >> 16, j = i & 65535;
        int b = j >> 10, k = j & (Hq - 1);
        g_hbuf[1][l0][b][k] = h0[l0 * Hq + k];
        int s = j & 3, lane = (j >> 2) & 31, kb = j >> 9;
        int col = kb * 8 + (lane & 3) + ((s >> 1) << 2);
        g_hbf[1][l0][j] = tftrunc(h0[l0 * Hq + col]);
    }
    gridbar();

    const int l = bx >> 5, idx = bx & 31;
    int gch = 0;   // per-CTA monotone chunk counter (drives mbarrier slot phases)
    for (int p = 0; p < NPH; ++p) {
        const int t = p - l;
        if (t >= 0 && t < Sq) {
            gru_stage(dyn, dynu, mbu, gch, l, t, idx * 32, bih, bhh);
            gch += 32;
            layerbar(l);
            sort_rows(dyn, l, idx);
            layerbar(l);
            fc_stage<0>(dyn, dynu, mbu, gch, l, t, idx * 64, outp); gch += 16;
            layerbar(l);
            fc_stage<1>(dyn, dynu, mbu, gch, l, t, idx * 64, outp); gch += 8;
            layerbar(l);
            fc_stage<2>(dyn, dynu, mbu, gch, l, t, idx * 64, outp); gch += 8;
            layerbar(l);
            fc_stage<3>(dyn, dynu, mbu, gch, l, t, idx * 32, outp); gch += 32;
        }
        gridbar();
    }

    // final hidden state hT (t=255 -> parity 1), layout (L,B,H)
    if (out_size >= Bq * Sq * Hq + Lq * Bq * Hq) {
        for (int i = gid; i < Lq * Bq * Hq; i += gsz)
            outp[(size_t)Bq * Sq * Hq + i] = __ldcg(&(&g_hbuf[1][0][0][0])[i]);
    }
}

// ---------------- launch ----------------
extern "C" void kernel_launch(void* const* d_in, const int* in_sizes, int n_in,
                              void* d_out, int out_size) {
    (void)in_sizes; (void)n_in;
    cudaFuncSetAttribute(fss_persist_kernel,
                         cudaFuncAttributeMaxDynamicSharedMemorySize, SMEM_BYTES);
    fss_persist_kernel<<<NCTA, NTHR, SMEM_BYTES>>>(
        (const float*)d_in[0], (const float*)d_in[1],
        (const float*)d_in[2], (const float*)d_in[3],
        (const float*)d_in[4], (const float*)d_in[5],
        (const float*)d_in[6], (const float*)d_in[7],
        (const float*)d_in[8], (const float*)d_in[9],
        (float*)d_out, out_size);
}

// round 15
// speedup vs baseline: 1.3510x; 1.0400x over previous
#include <cuda_runtime.h>
#include <cstdint>
#include <cstddef>

#define Bq 64
#define Sq 256
#define Hq 1024
#define Lq 4
#define H2q 2048
#define H3q 3072
#define NCTA 128
#define NTHR 512
#define NPH (Sq + Lq - 1)
#define GA 4096                       // A floats per chunk (64 rows x 64 k)
#define GB 6144                       // GRU B floats per chunk (96 rows x 64 k)
#define GSTG (GA + GB)                // floats per pipeline stage slot
#define SMEM_BYTES (4 * GSTG * 4)     // 163840 B

// ---------------- persistent device scratch ----------------
__device__ __align__(16) float g_hbuf[2][Lq][Bq][Hq];   // fp32 state (elementwise)
__device__ __align__(16) float g_hbf[2][Lq][Bq * Hq];   // tf32 fragment copy (GEMM A)
__device__ __align__(16) float g_hgru[Lq][Bq][Hq];      // fp32 GRU out (sort + gates)
__device__ __align__(16) float g_hgf[Lq][Bq * Hq];      // fragment copy (fc0 A)
__device__ __align__(16) float g_sf[Lq][Bq * Hq];       // sorted, fragment
__device__ __align__(16) float g_a0f[Lq][Bq * H2q];     // a0 shuffled, fragment
__device__ __align__(16) float g_a1f[Lq][Bq * H2q];     // a1 shuffled, fragment
__device__ __align__(16) float g_a2f[Lq][Bq * H2q];     // relu(a2), fragment
__device__ __align__(16) float g_xf[Sq * Bq * Hq];      // x, fragment per t
// fragment-major tf32 weights
__device__ __align__(16) float g_wihf[Lq * H3q * Hq];
__device__ __align__(16) float g_whhf[Lq * H3q * Hq];
__device__ __align__(16) float g_w0f[Lq * Hq * Hq];
__device__ __align__(16) float g_w1f[Lq * 512 * 512];
__device__ __align__(16) float g_w2f[Lq * 512 * 512];
__device__ __align__(16) float g_w3f[Lq * Hq * H2q];

__device__ unsigned g_cnt = 0;
__device__ volatile unsigned g_gen = 0;
__device__ unsigned g_lcnt[Lq] = {0, 0, 0, 0};
__device__ volatile unsigned g_lgen[Lq] = {0, 0, 0, 0};

// ---------------- helpers ----------------
__device__ __forceinline__ uint32_t f2tf(float f) {
    uint32_t u;
    asm("cvt.rna.tf32.f32 %0, %1;" : "=r"(u) : "f"(f));
    return u;
}
__device__ __forceinline__ float tftrunc(float f) { return __uint_as_float(f2tf(f)); }
__device__ __forceinline__ void mma8(float* c, uint32_t a0, uint32_t a1, uint32_t a2, uint32_t a3,
                                     uint32_t b0, uint32_t b1) {
    asm volatile(
        "mma.sync.aligned.m16n8k8.row.col.f32.tf32.tf32.f32 "
        "{%0,%1,%2,%3},{%4,%5,%6,%7},{%8,%9},{%0,%1,%2,%3};"
        : "+f"(c[0]), "+f"(c[1]), "+f"(c[2]), "+f"(c[3])
        : "r"(a0), "r"(a1), "r"(a2), "r"(a3), "r"(b0), "r"(b1));
}
__device__ __forceinline__ float sigmoidf_(float x) { return 1.0f / (1.0f + __expf(-x)); }

// ---------------- TMA bulk + mbarrier primitives ----------------
__device__ __forceinline__ void tbulk(uint32_t dst, const void* src, uint32_t bytes, uint32_t mbar) {
    asm volatile(
        "cp.async.bulk.shared::cluster.global.mbarrier::complete_tx::bytes [%0], [%1], %2, [%3];"
        :: "r"(dst), "l"(src), "r"(bytes), "r"(mbar) : "memory");
}
#define MBI(addr, cnt) asm volatile("mbarrier.init.shared.b64 [%0], %1;" :: "r"(addr), "r"(cnt) : "memory")
#define MBEXP(addr, tx) asm volatile("mbarrier.arrive.expect_tx.shared.b64 _, [%0], %1;" :: "r"(addr), "r"(tx) : "memory")
#define MBARR(addr) asm volatile("mbarrier.arrive.shared.b64 _, [%0];" :: "r"(addr) : "memory")
#define FENCE_PA() asm volatile("fence.proxy.async.shared::cta;" ::: "memory")

__device__ __forceinline__ void mb_wait(uint32_t mbar, uint32_t parity) {
    uint32_t done;
    asm volatile(
        "{\n\t.reg .pred p;\n\t"
        "mbarrier.try_wait.parity.acquire.cta.shared::cta.b64 p, [%1], %2;\n\t"
        "selp.b32 %0, 1, 0, p;\n\t}"
        : "=r"(done) : "r"(mbar), "r"(parity) : "memory");
    while (!done) {
        asm volatile(
            "{\n\t.reg .pred p;\n\t"
            "mbarrier.try_wait.parity.acquire.cta.shared::cta.b64 p, [%1], %2, 0x989680;\n\t"
            "selp.b32 %0, 1, 0, p;\n\t}"
            : "=r"(done) : "r"(mbar), "r"(parity) : "memory");
    }
}
// mbar layout in static smem: full[s] at mbu + s*8, empty[s] at mbu + 32 + s*8
#define MB_FULL(mbu, s)  ((mbu) + (s) * 8)
#define MB_EMPTY(mbu, s) ((mbu) + 32 + (s) * 8)
#define NCONS 15

// fragment index for 64-row A tensors: [kb=col>>3][mb4=row>>4][lane32][slot4]
__device__ __forceinline__ int afidx(int row, int col) {
    return ((((col >> 3) << 2) + (row >> 4)) * 32 + ((row & 7) * 4 + (col & 3))) * 4
         + ((((col & 7) >> 2) << 1) + ((row & 15) >> 3));
}

// ---------------- barriers ----------------
__device__ __forceinline__ void gridbar() {
    __threadfence();
    __syncthreads();
    if (threadIdx.x == 0) {
        unsigned gen = g_gen;
        if (atomicAdd(&g_cnt, 1u) == NCTA - 1) {
            g_cnt = 0;
            __threadfence();
            g_gen = gen + 1;
        } else {
            while (g_gen == gen) __nanosleep(64);
        }
    }
    __syncthreads();
}
__device__ __forceinline__ void layerbar(int l) {
    __threadfence();
    __syncthreads();
    if (threadIdx.x == 0) {
        unsigned gen = g_lgen[l];
        if (atomicAdd(&g_lcnt[l], 1u) == 31) {
            g_lcnt[l] = 0;
            __threadfence();
            g_lgen[l] = gen + 1;
        } else {
            while (g_lgen[l] == gen) __nanosleep(32);
        }
    }
    __syncthreads();
}

// ---------------- weight permute: row-major [N][K] -> fragment-major ----------------
__device__ __forceinline__ void permW(float* dst, const float* src, int N, int K,
                                      int gid, int gsz) {
    const int NB = N >> 3;
    const size_t tot = (size_t)N * K;
    for (size_t i = gid; i < tot; i += gsz) {
        int s = (int)(i & 3);
        int lane = (int)((i >> 2) & 31);
        int kb2 = (int)((i >> 7) & 3);
        size_t hi = i >> 9;
        int nb = (int)(hi % NB);
        int c = (int)(hi / NB);
        int r = nb * 8 + (lane >> 2);
        int k = c * 64 + kb2 * 16 + ((s >> 1) << 3) + ((s & 1) << 2) + (lane & 3);
        dst[i] = tftrunc(__ldg(src + (size_t)r * K + k));
    }
}

// m32n32 warp tile over kb2 range [KB2B, KB2B+KCNT): rows MB*32..+32 (32-float acc)
#define FRAG_T(APTR, BPTR, NBB, KB2B, KCNT, MB, ACC) { \
    const float* A_ = (APTR); \
    const uint4* Bf_ = (const uint4*)(BPTR); \
    _Pragma("unroll") \
    for (int kq = 0; kq < (KCNT); kq++) { \
        const int kb2_ = (KB2B) + kq; \
        uint4 b0_ = Bf_[(((NBB) + 0) * 4 + kb2_) * 32 + lane]; \
        uint4 b1_ = Bf_[(((NBB) + 1) * 4 + kb2_) * 32 + lane]; \
        uint4 b2_ = Bf_[(((NBB) + 2) * 4 + kb2_) * 32 + lane]; \
        uint4 b3_ = Bf_[(((NBB) + 3) * 4 + kb2_) * 32 + lane]; \
        _Pragma("unroll") \
        for (int pp = 0; pp < 2; pp++) { \
            _Pragma("unroll") \
            for (int mt = 0; mt < 2; mt++) { \
                uint4 aq = *(const uint4*)(A_ + ((kb2_ * 2 + pp) * 4 + (MB) * 2 + mt) * 128 + lane * 4); \
                mma8(ACC[mt][0], aq.x, aq.y, aq.z, aq.w, pp ? b0_.z : b0_.x, pp ? b0_.w : b0_.y); \
                mma8(ACC[mt][1], aq.x, aq.y, aq.z, aq.w, pp ? b1_.z : b1_.x, pp ? b1_.w : b1_.y); \
                mma8(ACC[mt][2], aq.x, aq.y, aq.z, aq.w, pp ? b2_.z : b2_.x, pp ? b2_.w : b2_.y); \
                mma8(ACC[mt][3], aq.x, aq.y, aq.z, aq.w, pp ? b3_.z : b3_.x, pp ? b3_.w : b3_.y); \
            } \
        } \
    } \
}

// ---------------- GRU stage: 32 H-cols/CTA -----------------------------------------
// 12 compute warps = 3 streams x 2 m32 x 2 k-split + TMA producer (warp 15).
// Stream 2 (N) reuses one 32-float acc: Ni partial dumped to static sNi at c==16.
__device__ __forceinline__ void gru_stage(float* dyn, float* sNi,
    uint32_t dynu, uint32_t mbu, int gch,
    int l, int t, int n0,
    const float* __restrict__ bih, const float* __restrict__ bhh)
{
    const int par = t & 1;
    const int tid = threadIdx.x;
    const int warp = tid >> 5, lane = tid & 31;
    const int st = warp >> 2, mb = (warp >> 1) & 1, ks = warp & 1;   // warp<12
    const int grp = lane >> 2, tig = lane & 3;

    const float* Af1 = (l == 0) ? (g_xf + (size_t)t * 65536) : g_hbf[par][l - 1];
    const float* Af2 = g_hbf[par ^ 1][l];
    const float* Wih_ = g_wihf + (size_t)l * H3q * Hq;
    const float* Whh_ = g_whhf + (size_t)l * H3q * Hq;

    float acc[2][4][4] = {};     // 32 floats: m32 x n32

    if (warp == 15) {
        if (lane == 0) {
            for (int c = 0; c < 32; c++) {
                const int g = gch + c;
                const int s = g & 3;
                mb_wait(MB_EMPTY(mbu, s), (((g >> 2) & 1) ^ 1));
                const uint32_t fb = MB_FULL(mbu, s);
                MBEXP(fb, 40960u);
                const uint32_t da = dynu + (uint32_t)s * (GSTG * 4);
                const float* as = (c < 16) ? (Af1 + (size_t)c * 4096)
                                           : (Af2 + (size_t)(c - 16) * 4096);
                tbulk(da, as, 16384u, fb);
                const float* wmat = (c < 16) ? Wih_ : Whh_;
                const int cc = c & 15;
#pragma unroll
                for (int s3 = 0; s3 < 3; s3++)
                    tbulk(da + GA * 4 + s3 * 8192,
                          wmat + ((size_t)(cc * 384 + s3 * 128 + (n0 >> 3))) * 512,
                          8192u, fb);
            }
        }
    } else {
        for (int c = 0; c < 16; c++) {
            const int g = gch + c;
            const int s = g & 3;
            mb_wait(MB_FULL(mbu, s), (g >> 2) & 1);
            if (warp < 12) {
                FRAG_T(dyn + s * GSTG, dyn + s * GSTG + GA + st * 2048, 0, ks * 2, 2, mb, acc);
            }
            if (lane == 0) MBARR(MB_EMPTY(mbu, s));
        }
        // ih half done: N-stream warps stage Ni partial into static buffer, reuse acc for Nh
        if (warp < 12 && st == 2) {
            float (*SN)[64][32] = (float(*)[64][32])sNi;
#pragma unroll
            for (int mt = 0; mt < 2; mt++)
#pragma unroll
                for (int ns = 0; ns < 4; ns++)
#pragma unroll
                    for (int e = 0; e < 4; e++) {
                        int row = mb * 32 + mt * 16 + grp + ((e >> 1) << 3);
                        int col = ns * 8 + tig * 2 + (e & 1);
                        SN[ks][row][col] = acc[mt][ns][e];
                        acc[mt][ns][e] = 0.0f;
                    }
        }
        for (int c = 16; c < 32; c++) {
            const int g = gch + c;
            const int s = g & 3;
            mb_wait(MB_FULL(mbu, s), (g >> 2) & 1);
            if (warp < 12) {
                FRAG_T(dyn + s * GSTG, dyn + s * GSTG + GA + st * 2048, 0, ks * 2, 2, mb, acc);
            }
            if (lane == 0) MBARR(MB_EMPTY(mbu, s));
        }
    }
    __syncthreads();

    // stage k-split partials: E2[stream 0..2][ks][64][32]  (stream 2 slot holds Nh)
    float (*E2)[2][64][32] = (float(*)[2][64][32])dyn;
    if (warp < 12) {
#pragma unroll
        for (int mt = 0; mt < 2; mt++)
#pragma unroll
            for (int ns = 0; ns < 4; ns++)
#pragma unroll
                for (int e = 0; e < 4; e++) {
                    int row = mb * 32 + mt * 16 + grp + ((e >> 1) << 3);
                    int col = ns * 8 + tig * 2 + (e & 1);
                    E2[st][ks][row][col] = acc[mt][ns][e];
                }
    }
    __syncthreads();

    const float* bi = bih + l * H3q;
    const float* bh = bhh + l * H3q;
    float (*SN)[64][32] = (float(*)[64][32])sNi;
#pragma unroll
    for (int e = 0; e < 4; e++) {
        int q = tid + e * 512;
        int m = q >> 5, n = q & 31, col = n0 + n;
        float gr = E2[0][0][m][n] + E2[0][1][m][n];
        float gz = E2[1][0][m][n] + E2[1][1][m][n];
        float gi = SN[0][m][n] + SN[1][m][n];
        float gh = E2[2][0][m][n] + E2[2][1][m][n];
        float r  = sigmoidf_(gr + __ldg(bi + col) + __ldg(bh + col));
        float z  = sigmoidf_(gz + __ldg(bi + Hq + col) + __ldg(bh + Hq + col));
        float nn = tanhf(gi + __ldg(bi + 2 * Hq + col)
                         + r * (gh + __ldg(bh + 2 * Hq + col)));
        float hp = __ldcg(&g_hbuf[par ^ 1][l][m][col]);
        float hv = (1.0f - z) * nn + z * hp;
        g_hgru[l][m][col] = hv;
        g_hgf[l][afidx(m, col)] = tftrunc(hv);
    }
    FENCE_PA();
    __syncthreads();
}

// ---------------- 2-rows-per-CTA bitonic sort (ascending, 1024 each) ------------
__device__ __forceinline__ void sort_rows(float* dyn, int l, int pair) {
    const int tid = threadIdx.x;
    const int sub = tid >> 8, tt = tid & 255;
    const int b = pair * 2 + sub;
    float* s = dyn + sub * 1024;
#pragma unroll
    for (int e = 0; e < 4; e++) s[tt + (e << 8)] = __ldcg(&g_hgru[l][b][tt + (e << 8)]);
    __syncthreads();
    for (int k = 2; k <= 1024; k <<= 1) {
        for (int j = k >> 1; j > 0; j >>= 1) {
#pragma unroll
            for (int e = 0; e < 2; e++) {
                int tc = tt + (e << 8);
                int pos = ((tc & ~(j - 1)) << 1) | (tc & (j - 1));
                int q = pos | j;
                bool up = ((pos & k) == 0);
                float a = s[pos], bb = s[q];
                if ((a > bb) == up) { s[pos] = bb; s[q] = a; }
            }
            __syncthreads();
        }
    }
#pragma unroll
    for (int e = 0; e < 4; e++) {
        int pos = tt + (e << 8);
        g_sf[l][afidx(b, pos)] = tftrunc(s[pos]);
    }
    FENCE_PA();
    __syncthreads();
}

// ---------------- generic FC stage (8 compute warps, m32n32 K-split, TMA) --------
// MODE 0: a0 = [h|sorted]@w0^T (K=1024, NT=64) -> stored shuffled
// MODE 1: a1 = a0s@w1^T        (K=512,  NT=64) -> stored shuffled
// MODE 2: a2 = relu(a1s@w2^T)  (K=512,  NT=64) -> linear
// MODE 3: h' = hgru*sigmoid(a2@w3^T) (K=2048, NT=32) -> hbuf + outs(l==3)
template <int MODE>
__device__ __forceinline__ void fc_stage(float* dyn, uint32_t dynu, uint32_t mbu, int gch,
                                         int l, int t, int n0, float* __restrict__ outp)
{
    constexpr int NCH = (MODE == 0) ? 16 : (MODE == 3 ? 32 : 8);
    constexpr int BFL = (MODE == 3) ? 2048 : 4096;
    constexpr int KCNT = (MODE == 3) ? 1 : 2;    // kb2 per warp per chunk

    const int tid = threadIdx.x;
    const int warp = tid >> 5, lane = tid & 31;
    const int grp = lane >> 2, tig = lane & 3;
    const int mb  = warp & 1;
    const int nbw = (MODE == 3) ? 0 : ((warp >> 1) & 1);
    const int ks  = (MODE == 3) ? (warp >> 1) : ((warp >> 2) & 1);

    const float* Af;
    if constexpr (MODE == 0)      Af = (n0 >= Hq) ? g_sf[l] : g_hgf[l];
    else if constexpr (MODE == 1) Af = g_a0f[l] + ((size_t)(n0 >> 9) << 15);
    else if constexpr (MODE == 2) Af = g_a1f[l] + ((size_t)(n0 >> 9) << 15);
    else                          Af = g_a2f[l];

    const float* Wf; int o0; int NBALL;
    if constexpr (MODE == 0)      { Wf = g_w0f + (size_t)l * Hq * Hq;   o0 = n0 & (Hq - 1); NBALL = 128; }
    else if constexpr (MODE == 1) { Wf = g_w1f + (size_t)l * 512 * 512; o0 = n0 & 511;      NBALL = 64; }
    else if constexpr (MODE == 2) { Wf = g_w2f + (size_t)l * 512 * 512; o0 = n0 & 511;      NBALL = 64; }
    else                          { Wf = g_w3f + (size_t)l * Hq * H2q;  o0 = n0;            NBALL = 128; }

    float acc[2][4][4] = {};     // 32 floats: m32 x n32

    if (warp == 15) {
        if (lane == 0) {
            for (int c = 0; c < NCH; c++) {
                const int g = gch + c;
                const int s = g & 3;
                mb_wait(MB_EMPTY(mbu, s), (((g >> 2) & 1) ^ 1));
                const uint32_t fb = MB_FULL(mbu, s);
                MBEXP(fb, 16384u + BFL * 4u);
                const uint32_t da = dynu + (uint32_t)s * (GSTG * 4);
                tbulk(da, Af + (size_t)c * 4096, 16384u, fb);
                tbulk(da + GA * 4, Wf + ((size_t)c * NBALL + (o0 >> 3)) * 512, BFL * 4u, fb);
            }
        }
    } else {
        for (int c = 0; c < NCH; c++) {
            const int g = gch + c;
            const int s = g & 3;
            mb_wait(MB_FULL(mbu, s), (g >> 2) & 1);
            if (warp < 8) {
                FRAG_T(dyn + s * GSTG, dyn + s * GSTG + GA, nbw * 4, ks * KCNT, KCNT, mb, acc);
            }
            if (lane == 0) MBARR(MB_EMPTY(mbu, s));
        }
    }
    __syncthreads();

    // stage K-split partials in smem, combine, write
    if constexpr (MODE == 3) {
        float (*Epi)[64][32] = (float(*)[64][32])dyn;   // [ks4][64][32] = 32 KB
        if (warp < 8) {
#pragma unroll
            for (int mt = 0; mt < 2; mt++)
#pragma unroll
                for (int ns = 0; ns < 4; ns++)
#pragma unroll
                    for (int e = 0; e < 4; e++) {
                        int row = mb * 32 + mt * 16 + grp + ((e >> 1) << 3);
                        int col = ns * 8 + tig * 2 + (e & 1);
                        Epi[ks][row][col] = acc[mt][ns][e];
                    }
        }
        __syncthreads();
#pragma unroll
        for (int i = 0; i < 4; i++) {
            int q = tid + i * 512;
            int row = q >> 5, col = q & 31, cg = n0 + col;
            float v = Epi[0][row][col] + Epi[1][row][col] + Epi[2][row][col] + Epi[3][row][col];
            float val = __ldcg(&g_hgru[l][row][cg]) * sigmoidf_(v);
            g_hbuf[t & 1][l][row][cg] = val;
            g_hbf[t & 1][l][afidx(row, cg)] = tftrunc(val);
            if (l == Lq - 1)
                outp[((size_t)row * Sq + t) * Hq + cg] = val;
        }
    } else {
        float (*Epi)[64][64] = (float(*)[64][64])dyn;   // [ks2][64][64] = 32 KB
        if (warp < 8) {
#pragma unroll
            for (int mt = 0; mt < 2; mt++)
#pragma unroll
                for (int ns = 0; ns < 4; ns++)
#pragma unroll
                    for (int e = 0; e < 4; e++) {
                        int row = mb * 32 + mt * 16 + grp + ((e >> 1) << 3);
                        int col = nbw * 32 + ns * 8 + tig * 2 + (e & 1);
                        Epi[ks][row][col] = acc[mt][ns][e];
                    }
        }
        __syncthreads();
#pragma unroll
        for (int i = 0; i < 8; i++) {
            int q = tid + i * 512;
            int row = q >> 6, col = q & 63, cg = n0 + col;
            float v = Epi[0][row][col] + Epi[1][row][col];
            if constexpr (MODE == 0) {
                int p = 4 * (cg & 511) + (cg >> 9);
                g_a0f[l][afidx(row, p)] = tftrunc(v);
            } else if constexpr (MODE == 1) {
                int p = 4 * (cg & 511) + (cg >> 9);
                g_a1f[l][afidx(row, p)] = tftrunc(v);
            } else {
                g_a2f[l][afidx(row, cg)] = tftrunc(fmaxf(v, 0.0f));
            }
        }
    }
    FENCE_PA();
    __syncthreads();
}

// ---------------- the single persistent kernel ----------------
__global__ void __launch_bounds__(NTHR, 1) fss_persist_kernel(
    const float* __restrict__ x, const float* __restrict__ h0,
    const float* __restrict__ Wih, const float* __restrict__ Whh,
    const float* __restrict__ bih, const float* __restrict__ bhh,
    const float* __restrict__ aw0, const float* __restrict__ aw1,
    const float* __restrict__ aw2, const float* __restrict__ aw3,
    float* __restrict__ outp, int out_size)
{
    extern __shared__ float dyn[];
    __shared__ __align__(16) uint64_t s_mb[8];
    __shared__ __align__(16) float s_ni[2 * 64 * 32];   // GRU Ni k-split staging
    const int bx = blockIdx.x, tid = threadIdx.x;
    const int gid = bx * NTHR + tid, gsz = NCTA * NTHR;
    const uint32_t dynu = (uint32_t)__cvta_generic_to_shared(dyn);
    const uint32_t mbu  = (uint32_t)__cvta_generic_to_shared(s_mb);

    // init pipeline mbarriers ONCE (full: 1 producer arrival+tx; empty: 15 warp arrivals)
    if (tid == 0) {
        for (int s = 0; s < 4; s++) {
            MBI(MB_FULL(mbu, s), 1);
            MBI(MB_EMPTY(mbu, s), NCONS);
        }
    }
    __syncthreads();

    // --- one-time-per-launch permutes (fragment-major, tf32 pre-rounded) ---
    for (int l0 = 0; l0 < Lq; l0++) {
        permW(g_wihf + (size_t)l0 * H3q * Hq, Wih + (size_t)l0 * H3q * Hq, H3q, Hq, gid, gsz);
        permW(g_whhf + (size_t)l0 * H3q * Hq, Whh + (size_t)l0 * H3q * Hq, H3q, Hq, gid, gsz);
        permW(g_w0f + (size_t)l0 * Hq * Hq,   aw0 + (size_t)l0 * Hq * Hq,  Hq, Hq, gid, gsz);
        permW(g_w1f + (size_t)l0 * 512 * 512, aw1 + (size_t)l0 * 512 * 512, 512, 512, gid, gsz);
        permW(g_w2f + (size_t)l0 * 512 * 512, aw2 + (size_t)l0 * 512 * 512, 512, 512, gid, gsz);
        permW(g_w3f + (size_t)l0 * Hq * H2q,  aw3 + (size_t)l0 * Hq * H2q, Hq, H2q, gid, gsz);
    }
    // x -> per-timestep fragment layout
    for (size_t i = gid; i < (size_t)Sq * 65536; i += gsz) {
        int j = (int)(i & 65535);
        int t = (int)(i >> 16);
        int s = j & 3, lane = (j >> 2) & 31, mb = (j >> 7) & 3, kb = j >> 9;
        int row = mb * 16 + (lane >> 2) + ((s & 1) << 3);
        int col = kb * 8 + (lane & 3) + ((s >> 1) << 2);
        g_xf[i] = tftrunc(__ldg(x + ((size_t)row * Sq + t) * Hq + col));
    }
    // h0 -> parity-1 buffers (linear + fragment); t=0 reads parity 1
    for (int i = gid; i < Lq * 65536; i += gsz) {
        int l0 = i >> 16, j = i & 65535;
        int b = j >> 10, k = j & (Hq - 1);
        g_hbuf[1][l0][b][k] = h0[l0 * Hq + k];
        int s = j & 3, lane = (j >> 2) & 31, kb = j >> 9;
        int col = kb * 8 + (lane & 3) + ((s >> 1) << 2);
        g_hbf[1][l0][j] = tftrunc(h0[l0 * Hq + col]);
    }
    gridbar();

    const int l = bx >> 5, idx = bx & 31;
    int gch = 0;   // per-CTA monotone chunk counter (drives mbarrier slot phases)
    for (int p = 0; p < NPH; ++p) {
        const int t = p - l;
        if (t >= 0 && t < Sq) {
            gru_stage(dyn, s_ni, dynu, mbu, gch, l, t, idx * 32, bih, bhh);
            gch += 32;
            layerbar(l);
            sort_rows(dyn, l, idx);
            layerbar(l);
            fc_stage<0>(dyn, dynu, mbu, gch, l, t, idx * 64, outp); gch += 16;
            layerbar(l);
            fc_stage<1>(dyn, dynu, mbu, gch, l, t, idx * 64, outp); gch += 8;
            layerbar(l);
            fc_stage<2>(dyn, dynu, mbu, gch, l, t, idx * 64, outp); gch += 8;
            layerbar(l);
            fc_stage<3>(dyn, dynu, mbu, gch, l, t, idx * 32, outp); gch += 32;
        }
        gridbar();
    }

    // final hidden state hT (t=255 -> parity 1), layout (L,B,H)
    if (out_size >= Bq * Sq * Hq + Lq * Bq * Hq) {
        for (int i = gid; i < Lq * Bq * Hq; i += gsz)
            outp[(size_t)Bq * Sq * Hq + i] = __ldcg(&(&g_hbuf[1][0][0][0])[i]);
    }
}

// ---------------- launch ----------------
extern "C" void kernel_launch(void* const* d_in, const int* in_sizes, int n_in,
                              void* d_out, int out_size) {
    (void)in_sizes; (void)n_in;
    cudaFuncSetAttribute(fss_persist_kernel,
                         cudaFuncAttributeMaxDynamicSharedMemorySize, SMEM_BYTES);
    fss_persist_kernel<<<NCTA, NTHR, SMEM_BYTES>>>(
        (const float*)d_in[0], (const float*)d_in[1],
        (const float*)d_in[2], (const float*)d_in[3],
        (const float*)d_in[4], (const float*)d_in[5],
        (const float*)d_in[6], (const float*)d_in[7],
        (const float*)d_in[8], (const float*)d_in[9],
        (float*)d_out, out_size);
}

// round 16
// speedup vs baseline: 1.8072x; 1.3376x over previous
#include <cuda_runtime.h>
#include <cuda_fp16.h>
#include <cstdint>
#include <cstddef>

#define Bq 64
#define Sq 256
#define Hq 1024
#define Lq 4
#define H2q 2048
#define H3q 3072
#define NCTA 128
#define NTHR 512
#define NPH (Sq + Lq - 1)
#define SLOTB 20480                   // bytes per pipeline slot: A 8KB + B up to 12KB
#define SMEM_BYTES (4 * SLOTB)        // 81920 B

// ---------------- persistent device scratch ----------------
__device__ __align__(16) float  g_hbuf[2][Lq][Bq][Hq];  // fp32 state (elementwise)
__device__ __align__(16) __half g_hbf[2][Lq][Bq * Hq];  // fp16 fragment copy (GRU A)
__device__ __align__(16) float  g_hgru[Lq][Bq][Hq];     // fp32 GRU out (sort + gates)
__device__ __align__(16) __half g_hgf[Lq][Bq * Hq];     // fragment copy (fc0 A)
__device__ __align__(16) __half g_sf[Lq][Bq * Hq];      // sorted, fragment
__device__ __align__(16) __half g_a0f[Lq][Bq * H2q];    // a0 shuffled, fragment
__device__ __align__(16) __half g_a1f[Lq][Bq * H2q];    // a1 shuffled, fragment
__device__ __align__(16) __half g_a2f[Lq][Bq * H2q];    // relu(a2), fragment
__device__ __align__(16) __half g_xf[Sq * Bq * Hq];     // x, fragment per t
// fragment-major fp16 weights
__device__ __align__(16) __half g_wihf[Lq * H3q * Hq];
__device__ __align__(16) __half g_whhf[Lq * H3q * Hq];
__device__ __align__(16) __half g_w0f[Lq * Hq * Hq];
__device__ __align__(16) __half g_w1f[Lq * 512 * 512];
__device__ __align__(16) __half g_w2f[Lq * 512 * 512];
__device__ __align__(16) __half g_w3f[Lq * Hq * H2q];

__device__ unsigned g_cnt = 0;
__device__ volatile unsigned g_gen = 0;
__device__ unsigned g_lcnt[Lq] = {0, 0, 0, 0};
__device__ volatile unsigned g_lgen[Lq] = {0, 0, 0, 0};

// ---------------- helpers ----------------
__device__ __forceinline__ void mma16(float* c, uint32_t a0, uint32_t a1, uint32_t a2, uint32_t a3,
                                      uint32_t b0, uint32_t b1) {
    asm volatile(
        "mma.sync.aligned.m16n8k16.row.col.f32.f16.f16.f32 "
        "{%0,%1,%2,%3},{%4,%5,%6,%7},{%8,%9},{%0,%1,%2,%3};"
        : "+f"(c[0]), "+f"(c[1]), "+f"(c[2]), "+f"(c[3])
        : "r"(a0), "r"(a1), "r"(a2), "r"(a3), "r"(b0), "r"(b1));
}
__device__ __forceinline__ float sigmoidf_(float x) { return 1.0f / (1.0f + __expf(-x)); }

// ---------------- TMA bulk + mbarrier primitives ----------------
__device__ __forceinline__ void tbulk(uint32_t dst, const void* src, uint32_t bytes, uint32_t mbar) {
    asm volatile(
        "cp.async.bulk.shared::cluster.global.mbarrier::complete_tx::bytes [%0], [%1], %2, [%3];"
        :: "r"(dst), "l"(src), "r"(bytes), "r"(mbar) : "memory");
}
#define MBI(addr, cnt) asm volatile("mbarrier.init.shared.b64 [%0], %1;" :: "r"(addr), "r"(cnt) : "memory")
#define MBEXP(addr, tx) asm volatile("mbarrier.arrive.expect_tx.shared.b64 _, [%0], %1;" :: "r"(addr), "r"(tx) : "memory")
#define MBARR(addr) asm volatile("mbarrier.arrive.shared.b64 _, [%0];" :: "r"(addr) : "memory")
#define FENCE_PA() asm volatile("fence.proxy.async.shared::cta;" ::: "memory")

__device__ __forceinline__ void mb_wait(uint32_t mbar, uint32_t parity) {
    uint32_t done;
    asm volatile(
        "{\n\t.reg .pred p;\n\t"
        "mbarrier.try_wait.parity.acquire.cta.shared::cta.b64 p, [%1], %2;\n\t"
        "selp.b32 %0, 1, 0, p;\n\t}"
        : "=r"(done) : "r"(mbar), "r"(parity) : "memory");
    while (!done) {
        asm volatile(
            "{\n\t.reg .pred p;\n\t"
            "mbarrier.try_wait.parity.acquire.cta.shared::cta.b64 p, [%1], %2, 0x989680;\n\t"
            "selp.b32 %0, 1, 0, p;\n\t}"
            : "=r"(done) : "r"(mbar), "r"(parity) : "memory");
    }
}
#define MB_FULL(mbu, s)  ((mbu) + (s) * 8)
#define MB_EMPTY(mbu, s) ((mbu) + 32 + (s) * 8)
#define NCONS 15

// fp16 A-fragment index (64-row tensors), matches mma.m16n8k16 A lane map:
// [c=col>>6][q=(col>>4)&3][mb=row>>4][lane][slot*2+h] ; lane=(row&7)*4+((col>>1)&3)
// slot = ((col>>3)&1)*2 + ((row>>3)&1)
__device__ __forceinline__ int afidx16(int row, int col) {
    int c = col >> 6, q = (col >> 4) & 3, mb = row >> 4;
    int lane = ((row & 7) << 2) | ((col >> 1) & 3);
    int slot = (((col >> 3) & 1) << 1) | ((row >> 3) & 1);
    return ((((c * 4 + q) * 4 + mb) * 32 + lane) << 3) + slot * 2 + (col & 1);
}

// ---------------- barriers ----------------
__device__ __forceinline__ void gridbar() {
    __threadfence();
    __syncthreads();
    if (threadIdx.x == 0) {
        unsigned gen = g_gen;
        if (atomicAdd(&g_cnt, 1u) == NCTA - 1) {
            g_cnt = 0;
            __threadfence();
            g_gen = gen + 1;
        } else {
            while (g_gen == gen) __nanosleep(64);
        }
    }
    __syncthreads();
}
__device__ __forceinline__ void layerbar(int l) {
    __threadfence();
    __syncthreads();
    if (threadIdx.x == 0) {
        unsigned gen = g_lgen[l];
        if (atomicAdd(&g_lcnt[l], 1u) == 31) {
            g_lcnt[l] = 0;
            __threadfence();
            g_lgen[l] = gen + 1;
        } else {
            while (g_lgen[l] == gen) __nanosleep(32);
        }
    }
    __syncthreads();
}

// ---------------- weight permute: row-major [N][K] -> fp16 B-fragment-major ---------
// layout: [c(K64)][nb(N/8)][q(4)][lane(32)][4 halves]; half i:
// hh=i&3, lane=(i>>2)&31, q=(i>>7)&3, nb=(i>>9)%NB, c=(i>>9)/NB
// n = nb*8 + (lane>>2); k = c*64 + q*16 + 2*(lane&3) + ((hh>>1)<<3) + (hh&1)
__device__ __forceinline__ void permW16(__half* dst, const float* src, int N, int K,
                                        int gid, int gsz) {
    const int NB = N >> 3;
    const size_t tot = (size_t)N * K;
    for (size_t i = gid; i < tot; i += gsz) {
        int hh = (int)(i & 3);
        int lane = (int)((i >> 2) & 31);
        int q = (int)((i >> 7) & 3);
        size_t hi = i >> 9;
        int nb = (int)(hi % NB);
        int c = (int)(hi / NB);
        int n = nb * 8 + (lane >> 2);
        int k = c * 64 + q * 16 + ((lane & 3) << 1) + ((hh >> 1) << 3) + (hh & 1);
        dst[i] = __float2half(__ldg(src + (size_t)n * K + k));
    }
}

// fp16 m32n32 warp tile over q (kb16) range [QB, QB+QCNT): rows MB*32..+32
#define FRAG16_T(APTR, BPTR, NBB, QB, QCNT, MB, ACC) { \
    const uint4* Aq_ = (const uint4*)(APTR); \
    const uint2* Bq_ = (const uint2*)(BPTR); \
    _Pragma("unroll") \
    for (int qq = 0; qq < (QCNT); qq++) { \
        const int q_ = (QB) + qq; \
        uint2 b0_ = Bq_[(((NBB) + 0) * 4 + q_) * 32 + lane]; \
        uint2 b1_ = Bq_[(((NBB) + 1) * 4 + q_) * 32 + lane]; \
        uint2 b2_ = Bq_[(((NBB) + 2) * 4 + q_) * 32 + lane]; \
        uint2 b3_ = Bq_[(((NBB) + 3) * 4 + q_) * 32 + lane]; \
        _Pragma("unroll") \
        for (int mt = 0; mt < 2; mt++) { \
            uint4 aq = Aq_[(q_ * 4 + (MB) * 2 + mt) * 32 + lane]; \
            mma16(ACC[mt][0], aq.x, aq.y, aq.z, aq.w, b0_.x, b0_.y); \
            mma16(ACC[mt][1], aq.x, aq.y, aq.z, aq.w, b1_.x, b1_.y); \
            mma16(ACC[mt][2], aq.x, aq.y, aq.z, aq.w, b2_.x, b2_.y); \
            mma16(ACC[mt][3], aq.x, aq.y, aq.z, aq.w, b3_.x, b3_.y); \
        } \
    } \
}

#define SLOT_A(dynp, s) ((const __half*)((const char*)(dynp) + (s) * SLOTB))
#define SLOT_B(dynp, s) ((const __half*)((const char*)(dynp) + (s) * SLOTB + 8192))

// ---------------- GRU stage: 32 H-cols/CTA -----------------------------------------
// 12 compute warps = 3 streams x 2 m32 x 2 k-split + TMA producer (warp 15).
__device__ __forceinline__ void gru_stage(float* dyn, float* sNi,
    uint32_t dynu, uint32_t mbu, int gch,
    int l, int t, int n0,
    const float* __restrict__ bih, const float* __restrict__ bhh)
{
    const int par = t & 1;
    const int tid = threadIdx.x;
    const int warp = tid >> 5, lane = tid & 31;
    const int st = warp >> 2, mb = (warp >> 1) & 1, ks = warp & 1;   // warp<12
    const int grp = lane >> 2, tig = lane & 3;

    const __half* Af1 = (l == 0) ? (g_xf + (size_t)t * 65536) : g_hbf[par][l - 1];
    const __half* Af2 = g_hbf[par ^ 1][l];
    const __half* Wih_ = g_wihf + (size_t)l * H3q * Hq;
    const __half* Whh_ = g_whhf + (size_t)l * H3q * Hq;

    float acc[2][4][4] = {};     // 32 floats: m32 x n32

    if (warp == 15) {
        if (lane == 0) {
            for (int c = 0; c < 32; c++) {
                const int g = gch + c;
                const int s = g & 3;
                mb_wait(MB_EMPTY(mbu, s), (((g >> 2) & 1) ^ 1));
                const uint32_t fb = MB_FULL(mbu, s);
                MBEXP(fb, 20480u);
                const uint32_t da = dynu + (uint32_t)s * SLOTB;
                const __half* as = (c < 16) ? (Af1 + (size_t)c * 4096)
                                            : (Af2 + (size_t)(c - 16) * 4096);
                tbulk(da, as, 8192u, fb);
                const __half* wmat = (c < 16) ? Wih_ : Whh_;
                const int cc = c & 15;
#pragma unroll
                for (int s3 = 0; s3 < 3; s3++)
                    tbulk(da + 8192 + s3 * 4096,
                          wmat + ((size_t)(cc * 384 + s3 * 128 + (n0 >> 3))) * 512,
                          4096u, fb);
            }
        }
    } else {
        for (int c = 0; c < 16; c++) {
            const int g = gch + c;
            const int s = g & 3;
            mb_wait(MB_FULL(mbu, s), (g >> 2) & 1);
            if (warp < 12) {
                FRAG16_T(SLOT_A(dyn, s), SLOT_B(dyn, s), st * 4, ks * 2, 2, mb, acc);
            }
            if (lane == 0) MBARR(MB_EMPTY(mbu, s));
        }
        // ih half done: N-stream warps stage Ni partial, reuse acc for Nh
        if (warp < 12 && st == 2) {
            float (*SN)[64][32] = (float(*)[64][32])sNi;
#pragma unroll
            for (int mt = 0; mt < 2; mt++)
#pragma unroll
                for (int ns = 0; ns < 4; ns++)
#pragma unroll
                    for (int e = 0; e < 4; e++) {
                        int row = mb * 32 + mt * 16 + grp + ((e >> 1) << 3);
                        int col = ns * 8 + tig * 2 + (e & 1);
                        SN[ks][row][col] = acc[mt][ns][e];
                        acc[mt][ns][e] = 0.0f;
                    }
        }
        for (int c = 16; c < 32; c++) {
            const int g = gch + c;
            const int s = g & 3;
            mb_wait(MB_FULL(mbu, s), (g >> 2) & 1);
            if (warp < 12) {
                FRAG16_T(SLOT_A(dyn, s), SLOT_B(dyn, s), st * 4, ks * 2, 2, mb, acc);
            }
            if (lane == 0) MBARR(MB_EMPTY(mbu, s));
        }
    }
    __syncthreads();

    // stage k-split partials: E2[stream 0..2][ks][64][32]  (stream 2 slot holds Nh)
    float (*E2)[2][64][32] = (float(*)[2][64][32])dyn;
    if (warp < 12) {
#pragma unroll
        for (int mt = 0; mt < 2; mt++)
#pragma unroll
            for (int ns = 0; ns < 4; ns++)
#pragma unroll
                for (int e = 0; e < 4; e++) {
                    int row = mb * 32 + mt * 16 + grp + ((e >> 1) << 3);
                    int col = ns * 8 + tig * 2 + (e & 1);
                    E2[st][ks][row][col] = acc[mt][ns][e];
                }
    }
    __syncthreads();

    const float* bi = bih + l * H3q;
    const float* bh = bhh + l * H3q;
    float (*SN)[64][32] = (float(*)[64][32])sNi;
#pragma unroll
    for (int e = 0; e < 4; e++) {
        int q = tid + e * 512;
        int m = q >> 5, n = q & 31, col = n0 + n;
        float gr = E2[0][0][m][n] + E2[0][1][m][n];
        float gz = E2[1][0][m][n] + E2[1][1][m][n];
        float gi = SN[0][m][n] + SN[1][m][n];
        float gh = E2[2][0][m][n] + E2[2][1][m][n];
        float r  = sigmoidf_(gr + __ldg(bi + col) + __ldg(bh + col));
        float z  = sigmoidf_(gz + __ldg(bi + Hq + col) + __ldg(bh + Hq + col));
        float nn = tanhf(gi + __ldg(bi + 2 * Hq + col)
                         + r * (gh + __ldg(bh + 2 * Hq + col)));
        float hp = __ldcg(&g_hbuf[par ^ 1][l][m][col]);
        float hv = (1.0f - z) * nn + z * hp;
        g_hgru[l][m][col] = hv;
        g_hgf[l][afidx16(m, col)] = __float2half(hv);
    }
    FENCE_PA();
    __syncthreads();
}

// ---------------- 2-rows-per-CTA bitonic sort (ascending, 1024 each) ------------
__device__ __forceinline__ void sort_rows(float* dyn, int l, int pair) {
    const int tid = threadIdx.x;
    const int sub = tid >> 8, tt = tid & 255;
    const int b = pair * 2 + sub;
    float* s = dyn + sub * 1024;
#pragma unroll
    for (int e = 0; e < 4; e++) s[tt + (e << 8)] = __ldcg(&g_hgru[l][b][tt + (e << 8)]);
    __syncthreads();
    for (int k = 2; k <= 1024; k <<= 1) {
        for (int j = k >> 1; j > 0; j >>= 1) {
#pragma unroll
            for (int e = 0; e < 2; e++) {
                int tc = tt + (e << 8);
                int pos = ((tc & ~(j - 1)) << 1) | (tc & (j - 1));
                int q = pos | j;
                bool up = ((pos & k) == 0);
                float a = s[pos], bb = s[q];
                if ((a > bb) == up) { s[pos] = bb; s[q] = a; }
            }
            __syncthreads();
        }
    }
#pragma unroll
    for (int e = 0; e < 4; e++) {
        int pos = tt + (e << 8);
        g_sf[l][afidx16(b, pos)] = __float2half(s[pos]);
    }
    FENCE_PA();
    __syncthreads();
}

// ---------------- generic FC stage (8 compute warps, m32n32 K-split, TMA) --------
// MODE 0: a0 = [h|sorted]@w0^T (K=1024, NT=64) -> stored shuffled
// MODE 1: a1 = a0s@w1^T        (K=512,  NT=64) -> stored shuffled
// MODE 2: a2 = relu(a1s@w2^T)  (K=512,  NT=64) -> linear
// MODE 3: h' = hgru*sigmoid(a2@w3^T) (K=2048, NT=32) -> hbuf + outs(l==3)
template <int MODE>
__device__ __forceinline__ void fc_stage(float* dyn, uint32_t dynu, uint32_t mbu, int gch,
                                         int l, int t, int n0, float* __restrict__ outp)
{
    constexpr int NCH = (MODE == 0) ? 16 : (MODE == 3 ? 32 : 8);
    constexpr uint32_t BFLB = (MODE == 3) ? 4096u : 8192u;   // B bytes per chunk
    constexpr int QCNT = (MODE == 3) ? 1 : 2;

    const int tid = threadIdx.x;
    const int warp = tid >> 5, lane = tid & 31;
    const int grp = lane >> 2, tig = lane & 3;
    const int mb  = warp & 1;
    const int nbw = (MODE == 3) ? 0 : ((warp >> 1) & 1);
    const int ks  = (MODE == 3) ? (warp >> 1) : ((warp >> 2) & 1);

    const __half* Af;
    if constexpr (MODE == 0)      Af = (n0 >= Hq) ? g_sf[l] : g_hgf[l];
    else if constexpr (MODE == 1) Af = g_a0f[l] + ((size_t)(n0 >> 9) << 15);
    else if constexpr (MODE == 2) Af = g_a1f[l] + ((size_t)(n0 >> 9) << 15);
    else                          Af = g_a2f[l];

    const __half* Wf; int o0; int NBALL;
    if constexpr (MODE == 0)      { Wf = g_w0f + (size_t)l * Hq * Hq;   o0 = n0 & (Hq - 1); NBALL = 128; }
    else if constexpr (MODE == 1) { Wf = g_w1f + (size_t)l * 512 * 512; o0 = n0 & 511;      NBALL = 64; }
    else if constexpr (MODE == 2) { Wf = g_w2f + (size_t)l * 512 * 512; o0 = n0 & 511;      NBALL = 64; }
    else                          { Wf = g_w3f + (size_t)l * Hq * H2q;  o0 = n0;            NBALL = 128; }

    float acc[2][4][4] = {};     // 32 floats: m32 x n32

    if (warp == 15) {
        if (lane == 0) {
            for (int c = 0; c < NCH; c++) {
                const int g = gch + c;
                const int s = g & 3;
                mb_wait(MB_EMPTY(mbu, s), (((g >> 2) & 1) ^ 1));
                const uint32_t fb = MB_FULL(mbu, s);
                MBEXP(fb, 8192u + BFLB);
                const uint32_t da = dynu + (uint32_t)s * SLOTB;
                tbulk(da, Af + (size_t)c * 4096, 8192u, fb);
                tbulk(da + 8192, Wf + ((size_t)c * NBALL + (o0 >> 3)) * 512, BFLB, fb);
            }
        }
    } else {
        for (int c = 0; c < NCH; c++) {
            const int g = gch + c;
            const int s = g & 3;
            mb_wait(MB_FULL(mbu, s), (g >> 2) & 1);
            if (warp < 8) {
                FRAG16_T(SLOT_A(dyn, s), SLOT_B(dyn, s), nbw * 4, ks * QCNT, QCNT, mb, acc);
            }
            if (lane == 0) MBARR(MB_EMPTY(mbu, s));
        }
    }
    __syncthreads();

    // stage K-split partials in smem, combine, write
    if constexpr (MODE == 3) {
        float (*Epi)[64][32] = (float(*)[64][32])dyn;   // [ks4][64][32] = 32 KB
        if (warp < 8) {
#pragma unroll
            for (int mt = 0; mt < 2; mt++)
#pragma unroll
                for (int ns = 0; ns < 4; ns++)
#pragma unroll
                    for (int e = 0; e < 4; e++) {
                        int row = mb * 32 + mt * 16 + grp + ((e >> 1) << 3);
                        int col = ns * 8 + tig * 2 + (e & 1);
                        Epi[ks][row][col] = acc[mt][ns][e];
                    }
        }
        __syncthreads();
#pragma unroll
        for (int i = 0; i < 4; i++) {
            int q = tid + i * 512;
            int row = q >> 5, col = q & 31, cg = n0 + col;
            float v = Epi[0][row][col] + Epi[1][row][col] + Epi[2][row][col] + Epi[3][row][col];
            float val = __ldcg(&g_hgru[l][row][cg]) * sigmoidf_(v);
            g_hbuf[t & 1][l][row][cg] = val;
            g_hbf[t & 1][l][afidx16(row, cg)] = __float2half(val);
            if (l == Lq - 1)
                outp[((size_t)row * Sq + t) * Hq + cg] = val;
        }
    } else {
        float (*Epi)[64][64] = (float(*)[64][64])dyn;   // [ks2][64][64] = 32 KB
        if (warp < 8) {
#pragma unroll
            for (int mt = 0; mt < 2; mt++)
#pragma unroll
                for (int ns = 0; ns < 4; ns++)
#pragma unroll
                    for (int e = 0; e < 4; e++) {
                        int row = mb * 32 + mt * 16 + grp + ((e >> 1) << 3);
                        int col = nbw * 32 + ns * 8 + tig * 2 + (e & 1);
                        Epi[ks][row][col] = acc[mt][ns][e];
                    }
        }
        __syncthreads();
#pragma unroll
        for (int i = 0; i < 8; i++) {
            int q = tid + i * 512;
            int row = q >> 6, col = q & 63, cg = n0 + col;
            float v = Epi[0][row][col] + Epi[1][row][col];
            if constexpr (MODE == 0) {
                int p = 4 * (cg & 511) + (cg >> 9);
                g_a0f[l][afidx16(row, p)] = __float2half(v);
            } else if constexpr (MODE == 1) {
                int p = 4 * (cg & 511) + (cg >> 9);
                g_a1f[l][afidx16(row, p)] = __float2half(v);
            } else {
                g_a2f[l][afidx16(row, cg)] = __float2half(fmaxf(v, 0.0f));
            }
        }
    }
    FENCE_PA();
    __syncthreads();
}

// ---------------- the single persistent kernel ----------------
__global__ void __launch_bounds__(NTHR, 1) fss_persist_kernel(
    const float* __restrict__ x, const float* __restrict__ h0,
    const float* __restrict__ Wih, const float* __restrict__ Whh,
    const float* __restrict__ bih, const float* __restrict__ bhh,
    const float* __restrict__ aw0, const float* __restrict__ aw1,
    const float* __restrict__ aw2, const float* __restrict__ aw3,
    float* __restrict__ outp, int out_size)
{
    extern __shared__ float dyn[];
    __shared__ __align__(16) uint64_t s_mb[8];
    __shared__ __align__(16) float s_ni[2 * 64 * 32];   // GRU Ni k-split staging
    const int bx = blockIdx.x, tid = threadIdx.x;
    const int gid = bx * NTHR + tid, gsz = NCTA * NTHR;
    const uint32_t dynu = (uint32_t)__cvta_generic_to_shared(dyn);
    const uint32_t mbu  = (uint32_t)__cvta_generic_to_shared(s_mb);

    if (tid == 0) {
        for (int s = 0; s < 4; s++) {
            MBI(MB_FULL(mbu, s), 1);
            MBI(MB_EMPTY(mbu, s), NCONS);
        }
    }
    __syncthreads();

    // --- one-time-per-launch permutes (fragment-major, fp16) ---
    for (int l0 = 0; l0 < Lq; l0++) {
        permW16(g_wihf + (size_t)l0 * H3q * Hq, Wih + (size_t)l0 * H3q * Hq, H3q, Hq, gid, gsz);
        permW16(g_whhf + (size_t)l0 * H3q * Hq, Whh + (size_t)l0 * H3q * Hq, H3q, Hq, gid, gsz);
        permW16(g_w0f + (size_t)l0 * Hq * Hq,   aw0 + (size_t)l0 * Hq * Hq,  Hq, Hq, gid, gsz);
        permW16(g_w1f + (size_t)l0 * 512 * 512, aw1 + (size_t)l0 * 512 * 512, 512, 512, gid, gsz);
        permW16(g_w2f + (size_t)l0 * 512 * 512, aw2 + (size_t)l0 * 512 * 512, 512, 512, gid, gsz);
        permW16(g_w3f + (size_t)l0 * Hq * H2q,  aw3 + (size_t)l0 * Hq * H2q, Hq, H2q, gid, gsz);
    }
    // x -> per-timestep fp16 fragment layout
    for (size_t i = gid; i < (size_t)Sq * 65536; i += gsz) {
        int j = (int)(i & 65535);
        int t = (int)(i >> 16);
        int h = j & 1, sl = (j >> 1) & 3, lane = (j >> 3) & 31;
        int mb = (j >> 8) & 3, q = (j >> 10) & 3, c = j >> 12;
        int row = mb * 16 + (lane >> 2) + ((sl & 1) << 3);
        int col = c * 64 + q * 16 + ((lane & 3) << 1) + ((sl >> 1) << 3) + h;
        g_xf[i] = __float2half(__ldg(x + ((size_t)row * Sq + t) * Hq + col));
    }
    // h0 -> parity-1 buffers (linear fp32 + fp16 fragment); t=0 reads parity 1
    for (int i = gid; i < Lq * 65536; i += gsz) {
        int l0 = i >> 16, j = i & 65535;
        int b = j >> 10, k = j & (Hq - 1);
        g_hbuf[1][l0][b][k] = h0[l0 * Hq + k];
        int h = j & 1, sl = (j >> 1) & 3, lane = (j >> 3) & 31;
        int q = (j >> 10) & 3, c = j >> 12;
        int col = c * 64 + q * 16 + ((lane & 3) << 1) + ((sl >> 1) << 3) + h;
        g_hbf[1][l0][j] = __float2half(h0[l0 * Hq + col]);
    }
    gridbar();

    const int l = bx >> 5, idx = bx & 31;
    int gch = 0;   // per-CTA monotone chunk counter (drives mbarrier slot phases)
    for (int p = 0; p < NPH; ++p) {
        const int t = p - l;
        if (t >= 0 && t < Sq) {
            gru_stage(dyn, s_ni, dynu, mbu, gch, l, t, idx * 32, bih, bhh);
            gch += 32;
            layerbar(l);
            sort_rows(dyn, l, idx);
            layerbar(l);
            fc_stage<0>(dyn, dynu, mbu, gch, l, t, idx * 64, outp); gch += 16;
            layerbar(l);
            fc_stage<1>(dyn, dynu, mbu, gch, l, t, idx * 64, outp); gch += 8;
            layerbar(l);
            fc_stage<2>(dyn, dynu, mbu, gch, l, t, idx * 64, outp); gch += 8;
            layerbar(l);
            fc_stage<3>(dyn, dynu, mbu, gch, l, t, idx * 32, outp); gch += 32;
        }
        gridbar();
    }

    // final hidden state hT (t=255 -> parity 1), layout (L,B,H)
    if (out_size >= Bq * Sq * Hq + Lq * Bq * Hq) {
        for (int i = gid; i < Lq * Bq * Hq; i += gsz)
            outp[(size_t)Bq * Sq * Hq + i] = __ldcg(&(&g_hbuf[1][0][0][0])[i]);
    }
}

// ---------------- launch ----------------
extern "C" void kernel_launch(void* const* d_in, const int* in_sizes, int n_in,
                              void* d_out, int out_size) {
    (void)in_sizes; (void)n_in;
    cudaFuncSetAttribute(fss_persist_kernel,
                         cudaFuncAttributeMaxDynamicSharedMemorySize, SMEM_BYTES);
    fss_persist_kernel<<<NCTA, NTHR, SMEM_BYTES>>>(
        (const float*)d_in[0], (const float*)d_in[1],
        (const float*)d_in[2], (const float*)d_in[3],
        (const float*)d_in[4], (const float*)d_in[5],
        (const float*)d_in[6], (const float*)d_in[7],
        (const float*)d_in[8], (const float*)d_in[9],
        (float*)d_out, out_size);
}

// round 17
// speedup vs baseline: 1.9723x; 1.0914x over previous
#include <cuda_runtime.h>
#include <cuda_fp16.h>
#include <cstdint>
#include <cstddef>

#define Bq 64
#define Sq 256
#define Hq 1024
#define Lq 4
#define H2q 2048
#define H3q 3072
#define NCTA 128
#define NTHR 512
#define NPH (Sq + Lq - 1)
#define SLOTB 40960                   // bytes per pipeline slot: A 16KB + B up to 24KB
#define SMEM_BYTES (4 * SLOTB)        // 163840 B

// ---------------- persistent device scratch ----------------
__device__ __align__(16) float  g_hbuf[2][Lq][Bq][Hq];  // fp32 state (elementwise)
__device__ __align__(16) __half g_hbf[2][Lq][Bq * Hq];  // fp16 fragment copy (GRU A)
__device__ __align__(16) float  g_hgru[Lq][Bq][Hq];     // fp32 GRU out (sort + gates)
__device__ __align__(16) __half g_hgf[Lq][Bq * Hq];     // fragment copy (fc0 A)
__device__ __align__(16) __half g_sf[Lq][Bq * Hq];      // sorted, fragment
__device__ __align__(16) __half g_a0f[Lq][Bq * H2q];    // a0 shuffled, fragment
__device__ __align__(16) __half g_a1f[Lq][Bq * H2q];    // a1 shuffled, fragment
__device__ __align__(16) __half g_a2f[Lq][Bq * H2q];    // relu(a2), fragment
__device__ __align__(16) __half g_xf[Sq * Bq * Hq];     // x, fragment per t
// fragment-major fp16 weights
__device__ __align__(16) __half g_wihf[Lq * H3q * Hq];
__device__ __align__(16) __half g_whhf[Lq * H3q * Hq];
__device__ __align__(16) __half g_w0f[Lq * Hq * Hq];
__device__ __align__(16) __half g_w1f[Lq * 512 * 512];
__device__ __align__(16) __half g_w2f[Lq * 512 * 512];
__device__ __align__(16) __half g_w3f[Lq * Hq * H2q];

__device__ unsigned g_cnt = 0;
__device__ volatile unsigned g_gen = 0;
__device__ unsigned g_lcnt[Lq] = {0, 0, 0, 0};
__device__ volatile unsigned g_lgen[Lq] = {0, 0, 0, 0};

// ---------------- helpers ----------------
__device__ __forceinline__ void mma16(float* c, uint32_t a0, uint32_t a1, uint32_t a2, uint32_t a3,
                                      uint32_t b0, uint32_t b1) {
    asm volatile(
        "mma.sync.aligned.m16n8k16.row.col.f32.f16.f16.f32 "
        "{%0,%1,%2,%3},{%4,%5,%6,%7},{%8,%9},{%0,%1,%2,%3};"
        : "+f"(c[0]), "+f"(c[1]), "+f"(c[2]), "+f"(c[3])
        : "r"(a0), "r"(a1), "r"(a2), "r"(a3), "r"(b0), "r"(b1));
}
__device__ __forceinline__ float sigmoidf_(float x) { return 1.0f / (1.0f + __expf(-x)); }

// ---------------- TMA bulk + mbarrier primitives ----------------
__device__ __forceinline__ void tbulk(uint32_t dst, const void* src, uint32_t bytes, uint32_t mbar) {
    asm volatile(
        "cp.async.bulk.shared::cluster.global.mbarrier::complete_tx::bytes [%0], [%1], %2, [%3];"
        :: "r"(dst), "l"(src), "r"(bytes), "r"(mbar) : "memory");
}
#define MBI(addr, cnt) asm volatile("mbarrier.init.shared.b64 [%0], %1;" :: "r"(addr), "r"(cnt) : "memory")
#define MBEXP(addr, tx) asm volatile("mbarrier.arrive.expect_tx.shared.b64 _, [%0], %1;" :: "r"(addr), "r"(tx) : "memory")
#define MBARR(addr) asm volatile("mbarrier.arrive.shared.b64 _, [%0];" :: "r"(addr) : "memory")
#define FENCE_PA() asm volatile("fence.proxy.async.shared::cta;" ::: "memory")

__device__ __forceinline__ void mb_wait(uint32_t mbar, uint32_t parity) {
    uint32_t done;
    asm volatile(
        "{\n\t.reg .pred p;\n\t"
        "mbarrier.try_wait.parity.acquire.cta.shared::cta.b64 p, [%1], %2;\n\t"
        "selp.b32 %0, 1, 0, p;\n\t}"
        : "=r"(done) : "r"(mbar), "r"(parity) : "memory");
    while (!done) {
        asm volatile(
            "{\n\t.reg .pred p;\n\t"
            "mbarrier.try_wait.parity.acquire.cta.shared::cta.b64 p, [%1], %2, 0x989680;\n\t"
            "selp.b32 %0, 1, 0, p;\n\t}"
            : "=r"(done) : "r"(mbar), "r"(parity) : "memory");
    }
}
#define MB_FULL(mbu, s)  ((mbu) + (s) * 8)
#define MB_EMPTY(mbu, s) ((mbu) + 32 + (s) * 8)
#define NCONS 15

// fp16 A-fragment index (64-row tensors), matches mma.m16n8k16 A lane map:
// [c=col>>6][q=(col>>4)&3][mb=row>>4][lane][slot*2+h]; lane=(row&7)*4+((col>>1)&3)
// slot = ((col>>3)&1)*2 + ((row>>3)&1)
__device__ __forceinline__ int afidx16(int row, int col) {
    int c = col >> 6, q = (col >> 4) & 3, mb = row >> 4;
    int lane = ((row & 7) << 2) | ((col >> 1) & 3);
    int slot = (((col >> 3) & 1) << 1) | ((row >> 3) & 1);
    return ((((c * 4 + q) * 4 + mb) * 32 + lane) << 3) + slot * 2 + (col & 1);
}

// ---------------- barriers ----------------
__device__ __forceinline__ void gridbar() {
    __threadfence();
    __syncthreads();
    if (threadIdx.x == 0) {
        unsigned gen = g_gen;
        if (atomicAdd(&g_cnt, 1u) == NCTA - 1) {
            g_cnt = 0;
            __threadfence();
            g_gen = gen + 1;
        } else {
            while (g_gen == gen) __nanosleep(64);
        }
    }
    __syncthreads();
}
__device__ __forceinline__ void layerbar(int l) {
    __threadfence();
    __syncthreads();
    if (threadIdx.x == 0) {
        unsigned gen = g_lgen[l];
        if (atomicAdd(&g_lcnt[l], 1u) == 31) {
            g_lcnt[l] = 0;
            __threadfence();
            g_lgen[l] = gen + 1;
        } else {
            while (g_lgen[l] == gen) __nanosleep(32);
        }
    }
    __syncthreads();
}

// ---------------- weight permute: row-major [N][K] -> fp16 B-fragment-major ---------
// layout: [c(K64)][nb(N/8)][q(4)][lane(32)][4 halves]
__device__ __forceinline__ void permW16(__half* dst, const float* src, int N, int K,
                                        int gid, int gsz) {
    const int NB = N >> 3;
    const size_t tot = (size_t)N * K;
    for (size_t i = gid; i < tot; i += gsz) {
        int hh = (int)(i & 3);
        int lane = (int)((i >> 2) & 31);
        int q = (int)((i >> 7) & 3);
        size_t hi = i >> 9;
        int nb = (int)(hi % NB);
        int c = (int)(hi / NB);
        int n = nb * 8 + (lane >> 2);
        int k = c * 64 + q * 16 + ((lane & 3) << 1) + ((hh >> 1) << 3) + (hh & 1);
        dst[i] = __float2half(__ldg(src + (size_t)n * K + k));
    }
}

// fp16 m32n32 warp tile over q range [QB, QB+QCNT) within one 64-k block
#define FRAG16_T(APTR, BPTR, NBB, QB, QCNT, MB, ACC) { \
    const uint4* Aq_ = (const uint4*)(APTR); \
    const uint2* Bq_ = (const uint2*)(BPTR); \
    _Pragma("unroll") \
    for (int qq = 0; qq < (QCNT); qq++) { \
        const int q_ = (QB) + qq; \
        uint2 b0_ = Bq_[(((NBB) + 0) * 4 + q_) * 32 + lane]; \
        uint2 b1_ = Bq_[(((NBB) + 1) * 4 + q_) * 32 + lane]; \
        uint2 b2_ = Bq_[(((NBB) + 2) * 4 + q_) * 32 + lane]; \
        uint2 b3_ = Bq_[(((NBB) + 3) * 4 + q_) * 32 + lane]; \
        _Pragma("unroll") \
        for (int mt = 0; mt < 2; mt++) { \
            uint4 aq = Aq_[(q_ * 4 + (MB) * 2 + mt) * 32 + lane]; \
            mma16(ACC[mt][0], aq.x, aq.y, aq.z, aq.w, b0_.x, b0_.y); \
            mma16(ACC[mt][1], aq.x, aq.y, aq.z, aq.w, b1_.x, b1_.y); \
            mma16(ACC[mt][2], aq.x, aq.y, aq.z, aq.w, b2_.x, b2_.y); \
            mma16(ACC[mt][3], aq.x, aq.y, aq.z, aq.w, b3_.x, b3_.y); \
        } \
    } \
}

#define SLOT_A(dynp, s) ((const __half*)((const char*)(dynp) + (s) * SLOTB))
#define SLOT_B(dynp, s) ((const __half*)((const char*)(dynp) + (s) * SLOTB + 16384))

// ---------------- GRU stage: 32 H-cols/CTA, K128 chunks ---------------------------
// 12 compute warps = 3 streams x 2 m32 x 2 k-split + TMA producer (warp 15).
// 16 chunks: 8 ih + 8 hh. Slot: A 16KB + B 24KB ([cpart2][stream3][2048 halves]).
__device__ __forceinline__ void gru_stage(float* dyn, float* sNi,
    uint32_t dynu, uint32_t mbu, int gch,
    int l, int t, int n0,
    const float* __restrict__ bih, const float* __restrict__ bhh)
{
    const int par = t & 1;
    const int tid = threadIdx.x;
    const int warp = tid >> 5, lane = tid & 31;
    const int st = warp >> 2, mb = (warp >> 1) & 1, ks = warp & 1;   // warp<12
    const int grp = lane >> 2, tig = lane & 3;

    const __half* Af1 = (l == 0) ? (g_xf + (size_t)t * 65536) : g_hbf[par][l - 1];
    const __half* Af2 = g_hbf[par ^ 1][l];
    const __half* Wih_ = g_wihf + (size_t)l * H3q * Hq;
    const __half* Whh_ = g_whhf + (size_t)l * H3q * Hq;

    float acc[2][4][4] = {};     // 32 floats: m32 x n32

    if (warp == 15) {
        if (lane == 0) {
            for (int c = 0; c < 16; c++) {
                const int g = gch + c;
                const int s = g & 3;
                mb_wait(MB_EMPTY(mbu, s), (((g >> 2) & 1) ^ 1));
                const uint32_t fb = MB_FULL(mbu, s);
                MBEXP(fb, 40960u);
                const uint32_t da = dynu + (uint32_t)s * SLOTB;
                const __half* as = (c < 8) ? (Af1 + (size_t)c * 8192)
                                           : (Af2 + (size_t)(c - 8) * 8192);
                tbulk(da, as, 16384u, fb);
                const __half* wmat = (c < 8) ? Wih_ : Whh_;
#pragma unroll
                for (int cp = 0; cp < 2; cp++) {
                    const int cc = ((c & 7) << 1) + cp;
#pragma unroll
                    for (int s3 = 0; s3 < 3; s3++)
                        tbulk(da + 16384 + (cp * 3 + s3) * 4096,
                              wmat + ((size_t)(cc * 384 + s3 * 128 + (n0 >> 3))) * 512,
                              4096u, fb);
                }
            }
        }
    } else {
        for (int c = 0; c < 8; c++) {
            const int g = gch + c;
            const int s = g & 3;
            mb_wait(MB_FULL(mbu, s), (g >> 2) & 1);
            if (warp < 12) {
#pragma unroll
                for (int cp = 0; cp < 2; cp++)
                    FRAG16_T(SLOT_A(dyn, s) + cp * 4096,
                             SLOT_B(dyn, s) + (cp * 3 + st) * 2048, 0, ks * 2, 2, mb, acc);
            }
            if (lane == 0) MBARR(MB_EMPTY(mbu, s));
        }
        // ih half done: N-stream warps stage Ni partial, reuse acc for Nh
        if (warp < 12 && st == 2) {
            float (*SN)[64][32] = (float(*)[64][32])sNi;
#pragma unroll
            for (int mt = 0; mt < 2; mt++)
#pragma unroll
                for (int ns = 0; ns < 4; ns++)
#pragma unroll
                    for (int e = 0; e < 4; e++) {
                        int row = mb * 32 + mt * 16 + grp + ((e >> 1) << 3);
                        int col = ns * 8 + tig * 2 + (e & 1);
                        SN[ks][row][col] = acc[mt][ns][e];
                        acc[mt][ns][e] = 0.0f;
                    }
        }
        for (int c = 8; c < 16; c++) {
            const int g = gch + c;
            const int s = g & 3;
            mb_wait(MB_FULL(mbu, s), (g >> 2) & 1);
            if (warp < 12) {
#pragma unroll
                for (int cp = 0; cp < 2; cp++)
                    FRAG16_T(SLOT_A(dyn, s) + cp * 4096,
                             SLOT_B(dyn, s) + (cp * 3 + st) * 2048, 0, ks * 2, 2, mb, acc);
            }
            if (lane == 0) MBARR(MB_EMPTY(mbu, s));
        }
    }
    __syncthreads();

    // stage k-split partials: E2[stream 0..2][ks][64][32]  (stream 2 slot holds Nh)
    float (*E2)[2][64][32] = (float(*)[2][64][32])dyn;
    if (warp < 12) {
#pragma unroll
        for (int mt = 0; mt < 2; mt++)
#pragma unroll
            for (int ns = 0; ns < 4; ns++)
#pragma unroll
                for (int e = 0; e < 4; e++) {
                    int row = mb * 32 + mt * 16 + grp + ((e >> 1) << 3);
                    int col = ns * 8 + tig * 2 + (e & 1);
                    E2[st][ks][row][col] = acc[mt][ns][e];
                }
    }
    __syncthreads();

    const float* bi = bih + l * H3q;
    const float* bh = bhh + l * H3q;
    float (*SN)[64][32] = (float(*)[64][32])sNi;
#pragma unroll
    for (int e = 0; e < 4; e++) {
        int q = tid + e * 512;
        int m = q >> 5, n = q & 31, col = n0 + n;
        float gr = E2[0][0][m][n] + E2[0][1][m][n];
        float gz = E2[1][0][m][n] + E2[1][1][m][n];
        float gi = SN[0][m][n] + SN[1][m][n];
        float gh = E2[2][0][m][n] + E2[2][1][m][n];
        float r  = sigmoidf_(gr + __ldg(bi + col) + __ldg(bh + col));
        float z  = sigmoidf_(gz + __ldg(bi + Hq + col) + __ldg(bh + Hq + col));
        float nn = tanhf(gi + __ldg(bi + 2 * Hq + col)
                         + r * (gh + __ldg(bh + 2 * Hq + col)));
        float hp = __ldcg(&g_hbuf[par ^ 1][l][m][col]);
        float hv = (1.0f - z) * nn + z * hp;
        g_hgru[l][m][col] = hv;
        g_hgf[l][afidx16(m, col)] = __float2half(hv);
    }
    FENCE_PA();
    __syncthreads();
}

// ---------------- 2-rows-per-CTA bitonic sort (ascending, 1024 each) ------------
__device__ __forceinline__ void sort_rows(float* dyn, int l, int pair) {
    const int tid = threadIdx.x;
    const int sub = tid >> 8, tt = tid & 255;
    const int b = pair * 2 + sub;
    float* s = dyn + sub * 1024;
#pragma unroll
    for (int e = 0; e < 4; e++) s[tt + (e << 8)] = __ldcg(&g_hgru[l][b][tt + (e << 8)]);
    __syncthreads();
    for (int k = 2; k <= 1024; k <<= 1) {
        for (int j = k >> 1; j > 0; j >>= 1) {
#pragma unroll
            for (int e = 0; e < 2; e++) {
                int tc = tt + (e << 8);
                int pos = ((tc & ~(j - 1)) << 1) | (tc & (j - 1));
                int q = pos | j;
                bool up = ((pos & k) == 0);
                float a = s[pos], bb = s[q];
                if ((a > bb) == up) { s[pos] = bb; s[q] = a; }
            }
            __syncthreads();
        }
    }
#pragma unroll
    for (int e = 0; e < 4; e++) {
        int pos = tt + (e << 8);
        g_sf[l][afidx16(b, pos)] = __float2half(s[pos]);
    }
    FENCE_PA();
    __syncthreads();
}

// ---------------- generic FC stage (8 compute warps, K128 chunks, TMA) ------------
// MODE 0: a0 = [h|sorted]@w0^T (K=1024, NT=64, 8 chunks)
// MODE 1: a1 = a0s@w1^T        (K=512,  NT=64, 4 chunks)
// MODE 2: a2 = relu(a1s@w2^T)  (K=512,  NT=64, 4 chunks)
// MODE 3: h' = hgru*sigmoid(a2@w3^T) (K=2048, NT=32, 16 chunks)
template <int MODE>
__device__ __forceinline__ void fc_stage(float* dyn, uint32_t dynu, uint32_t mbu, int gch,
                                         int l, int t, int n0, float* __restrict__ outp)
{
    constexpr int NCH = (MODE == 0) ? 8 : (MODE == 3 ? 16 : 4);
    constexpr uint32_t BFLB = (MODE == 3) ? 4096u : 8192u;   // B bytes per cpart
    constexpr int QB_  = (MODE == 3) ? 1 : 2;                // q per warp per cpart

    const int tid = threadIdx.x;
    const int warp = tid >> 5, lane = tid & 31;
    const int grp = lane >> 2, tig = lane & 3;
    const int mb  = warp & 1;
    const int nbw = (MODE == 3) ? 0 : ((warp >> 1) & 1);
    const int ks  = (MODE == 3) ? (warp >> 1) : ((warp >> 2) & 1);

    const __half* Af;
    if constexpr (MODE == 0)      Af = (n0 >= Hq) ? g_sf[l] : g_hgf[l];
    else if constexpr (MODE == 1) Af = g_a0f[l] + ((size_t)(n0 >> 9) << 15);
    else if constexpr (MODE == 2) Af = g_a1f[l] + ((size_t)(n0 >> 9) << 15);
    else                          Af = g_a2f[l];

    const __half* Wf; int o0; int NBALL;
    if constexpr (MODE == 0)      { Wf = g_w0f + (size_t)l * Hq * Hq;   o0 = n0 & (Hq - 1); NBALL = 128; }
    else if constexpr (MODE == 1) { Wf = g_w1f + (size_t)l * 512 * 512; o0 = n0 & 511;      NBALL = 64; }
    else if constexpr (MODE == 2) { Wf = g_w2f + (size_t)l * 512 * 512; o0 = n0 & 511;      NBALL = 64; }
    else                          { Wf = g_w3f + (size_t)l * Hq * H2q;  o0 = n0;            NBALL = 128; }

    float acc[2][4][4] = {};     // 32 floats: m32 x n32

    if (warp == 15) {
        if (lane == 0) {
            for (int c = 0; c < NCH; c++) {
                const int g = gch + c;
                const int s = g & 3;
                mb_wait(MB_EMPTY(mbu, s), (((g >> 2) & 1) ^ 1));
                const uint32_t fb = MB_FULL(mbu, s);
                MBEXP(fb, 16384u + 2u * BFLB);
                const uint32_t da = dynu + (uint32_t)s * SLOTB;
                tbulk(da, Af + (size_t)c * 8192, 16384u, fb);
#pragma unroll
                for (int cp = 0; cp < 2; cp++)
                    tbulk(da + 16384 + cp * BFLB,
                          Wf + ((size_t)((c * 2 + cp) * NBALL + (o0 >> 3))) * 512, BFLB, fb);
            }
        }
    } else {
        for (int c = 0; c < NCH; c++) {
            const int g = gch + c;
            const int s = g & 3;
            mb_wait(MB_FULL(mbu, s), (g >> 2) & 1);
            if (warp < 8) {
#pragma unroll
                for (int cp = 0; cp < 2; cp++)
                    FRAG16_T(SLOT_A(dyn, s) + cp * 4096,
                             SLOT_B(dyn, s) + cp * (BFLB / 2),
                             nbw * 4, ks * QB_, QB_, mb, acc);
            }
            if (lane == 0) MBARR(MB_EMPTY(mbu, s));
        }
    }
    __syncthreads();

    // stage K-split partials in smem, combine, write
    if constexpr (MODE == 3) {
        float (*Epi)[64][32] = (float(*)[64][32])dyn;   // [ks4][64][32] = 32 KB
        if (warp < 8) {
#pragma unroll
            for (int mt = 0; mt < 2; mt++)
#pragma unroll
                for (int ns = 0; ns < 4; ns++)
#pragma unroll
                    for (int e = 0; e < 4; e++) {
                        int row = mb * 32 + mt * 16 + grp + ((e >> 1) << 3);
                        int col = ns * 8 + tig * 2 + (e & 1);
                        Epi[ks][row][col] = acc[mt][ns][e];
                    }
        }
        __syncthreads();
#pragma unroll
        for (int i = 0; i < 4; i++) {
            int q = tid + i * 512;
            int row = q >> 5, col = q & 31, cg = n0 + col;
            float v = Epi[0][row][col] + Epi[1][row][col] + Epi[2][row][col] + Epi[3][row][col];
            float val = __ldcg(&g_hgru[l][row][cg]) * sigmoidf_(v);
            g_hbuf[t & 1][l][row][cg] = val;
            g_hbf[t & 1][l][afidx16(row, cg)] = __float2half(val);
            if (l == Lq - 1)
                outp[((size_t)row * Sq + t) * Hq + cg] = val;
        }
    } else {
        float (*Epi)[64][64] = (float(*)[64][64])dyn;   // [ks2][64][64] = 32 KB
        if (warp < 8) {
#pragma unroll
            for (int mt = 0; mt < 2; mt++)
#pragma unroll
                for (int ns = 0; ns < 4; ns++)
#pragma unroll
                    for (int e = 0; e < 4; e++) {
                        int row = mb * 32 + mt * 16 + grp + ((e >> 1) << 3);
                        int col = nbw * 32 + ns * 8 + tig * 2 + (e & 1);
                        Epi[ks][row][col] = acc[mt][ns][e];
                    }
        }
        __syncthreads();
#pragma unroll
        for (int i = 0; i < 8; i++) {
            int q = tid + i * 512;
            int row = q >> 6, col = q & 63, cg = n0 + col;
            float v = Epi[0][row][col] + Epi[1][row][col];
            if constexpr (MODE == 0) {
                int p = 4 * (cg & 511) + (cg >> 9);
                g_a0f[l][afidx16(row, p)] = __float2half(v);
            } else if constexpr (MODE == 1) {
                int p = 4 * (cg & 511) + (cg >> 9);
                g_a1f[l][afidx16(row, p)] = __float2half(v);
            } else {
                g_a2f[l][afidx16(row, cg)] = __float2half(fmaxf(v, 0.0f));
            }
        }
    }
    FENCE_PA();
    __syncthreads();
}

// ---------------- the single persistent kernel ----------------
__global__ void __launch_bounds__(NTHR, 1) fss_persist_kernel(
    const float* __restrict__ x, const float* __restrict__ h0,
    const float* __restrict__ Wih, const float* __restrict__ Whh,
    const float* __restrict__ bih, const float* __restrict__ bhh,
    const float* __restrict__ aw0, const float* __restrict__ aw1,
    const float* __restrict__ aw2, const float* __restrict__ aw3,
    float* __restrict__ outp, int out_size)
{
    extern __shared__ float dyn[];
    __shared__ __align__(16) uint64_t s_mb[8];
    __shared__ __align__(16) float s_ni[2 * 64 * 32];   // GRU Ni k-split staging
    const int bx = blockIdx.x, tid = threadIdx.x;
    const int gid = bx * NTHR + tid, gsz = NCTA * NTHR;
    const uint32_t dynu = (uint32_t)__cvta_generic_to_shared(dyn);
    const uint32_t mbu  = (uint32_t)__cvta_generic_to_shared(s_mb);

    if (tid == 0) {
        for (int s = 0; s < 4; s++) {
            MBI(MB_FULL(mbu, s), 1);
            MBI(MB_EMPTY(mbu, s), NCONS);
        }
    }
    __syncthreads();

    // --- one-time-per-launch permutes (fragment-major, fp16) ---
    for (int l0 = 0; l0 < Lq; l0++) {
        permW16(g_wihf + (size_t)l0 * H3q * Hq, Wih + (size_t)l0 * H3q * Hq, H3q, Hq, gid, gsz);
        permW16(g_whhf + (size_t)l0 * H3q * Hq, Whh + (size_t)l0 * H3q * Hq, H3q, Hq, gid, gsz);
        permW16(g_w0f + (size_t)l0 * Hq * Hq,   aw0 + (size_t)l0 * Hq * Hq,  Hq, Hq, gid, gsz);
        permW16(g_w1f + (size_t)l0 * 512 * 512, aw1 + (size_t)l0 * 512 * 512, 512, 512, gid, gsz);
        permW16(g_w2f + (size_t)l0 * 512 * 512, aw2 + (size_t)l0 * 512 * 512, 512, 512, gid, gsz);
        permW16(g_w3f + (size_t)l0 * Hq * H2q,  aw3 + (size_t)l0 * Hq * H2q, Hq, H2q, gid, gsz);
    }
    // x -> per-timestep fp16 fragment layout
    for (size_t i = gid; i < (size_t)Sq * 65536; i += gsz) {
        int j = (int)(i & 65535);
        int t = (int)(i >> 16);
        int h = j & 1, sl = (j >> 1) & 3, lane = (j >> 3) & 31;
        int mb = (j >> 8) & 3, q = (j >> 10) & 3, c = j >> 12;
        int row = mb * 16 + (lane >> 2) + ((sl & 1) << 3);
        int col = c * 64 + q * 16 + ((lane & 3) << 1) + ((sl >> 1) << 3) + h;
        g_xf[i] = __float2half(__ldg(x + ((size_t)row * Sq + t) * Hq + col));
    }
    // h0 -> parity-1 buffers (linear fp32 + fp16 fragment); t=0 reads parity 1
    for (int i = gid; i < Lq * 65536; i += gsz) {
        int l0 = i >> 16, j = i & 65535;
        int b = j >> 10, k = j & (Hq - 1);
        g_hbuf[1][l0][b][k] = h0[l0 * Hq + k];
        int h = j & 1, sl = (j >> 1) & 3, lane = (j >> 3) & 31;
        int q = (j >> 10) & 3, c = j >> 12;
        int col = c * 64 + q * 16 + ((lane & 3) << 1) + ((sl >> 1) << 3) + h;
        g_hbf[1][l0][j] = __float2half(h0[l0 * Hq + col]);
    }
    gridbar();

    const int l = bx >> 5, idx = bx & 31;
    int gch = 0;   // per-CTA monotone chunk counter (drives mbarrier slot phases)
    for (int p = 0; p < NPH; ++p) {
        const int t = p - l;
        if (t >= 0 && t < Sq) {
            gru_stage(dyn, s_ni, dynu, mbu, gch, l, t, idx * 32, bih, bhh);
            gch += 16;
            layerbar(l);
            sort_rows(dyn, l, idx);
            layerbar(l);
            fc_stage<0>(dyn, dynu, mbu, gch, l, t, idx * 64, outp); gch += 8;
            layerbar(l);
            fc_stage<1>(dyn, dynu, mbu, gch, l, t, idx * 64, outp); gch += 4;
            layerbar(l);
            fc_stage<2>(dyn, dynu, mbu, gch, l, t, idx * 64, outp); gch += 4;
            layerbar(l);
            fc_stage<3>(dyn, dynu, mbu, gch, l, t, idx * 32, outp); gch += 16;
        }
        gridbar();
    }

    // final hidden state hT (t=255 -> parity 1), layout (L,B,H)
    if (out_size >= Bq * Sq * Hq + Lq * Bq * Hq) {
        for (int i = gid; i < Lq * Bq * Hq; i += gsz)
            outp[(size_t)Bq * Sq * Hq + i] = __ldcg(&(&g_hbuf[1][0][0][0])[i]);
    }
}

// ---------------- launch ----------------
extern "C" void kernel_launch(void* const* d_in, const int* in_sizes, int n_in,
                              void* d_out, int out_size) {
    (void)in_sizes; (void)n_in;
    cudaFuncSetAttribute(fss_persist_kernel,
                         cudaFuncAttributeMaxDynamicSharedMemorySize, SMEM_BYTES);
    fss_persist_kernel<<<NCTA, NTHR, SMEM_BYTES>>>(
        (const float*)d_in[0], (const float*)d_in[1],
        (const float*)d_in[2], (const float*)d_in[3],
        (const float*)d_in[4], (const float*)d_in[5],
        (const float*)d_in[6], (const float*)d_in[7],
        (const float*)d_in[8], (const float*)d_in[9],
        (float*)d_out, out_size);
}